// round 7
// baseline (speedup 1.0000x reference)
#include <cuda_runtime.h>
#include <cuda_bf16.h>
#include <math.h>
#include <stdint.h>

// Problem constants
#define BS 4096
#define HL 20
#define NF 128
#define EF 128
#define TF 128
#define DM 640          // 3*NF + EF + TF
#define DIN 512         // DM - TF
#define NHEAD 2
#define DH 320          // DM / NHEAD
#define ODE_STEPS 8

// K-block interleave: position 4t+i within each 16-block holds original k=t+4i.
#define PERM(k) (((k) & ~15) | (((k) & 3) << 2) | (((k) & 15) >> 2))

// ---------------- scratch (device globals; no allocation allowed) ----------
__device__ float g_full [(size_t)BS*HL*DM];     // full_vals (tf32, K-permuted)
__device__ float g_nb   [(size_t)BS*HL*384];    // nb (tf32, K-permuted)
__device__ float g_kv   [(size_t)BS*HL*1280];   // k|v (GEMM output, normal)
__device__ float g_lef  [(size_t)BS*DIN];       // last_event_feat (tf32, K-perm)
__device__ float g_qlast[(size_t)BS*DM];
__device__ float g_ctx  [(size_t)BS*DM];        // (tf32, K-permuted)
__device__ float g_qh   [(size_t)BS*NF];
__device__ float g_khv  [(size_t)BS*HL*256];    // kh|vh fused (output, normal)
__device__ float g_gi   [(size_t)BS*384];
__device__ float g_hpr  [(size_t)BS*NF];
__device__ float g_odewT[NF*NF];
__device__ float g_ipw  [1920*640];             // tf32, K-permuted in_proj_w
__device__ float g_gwih [384*512];              // tf32, K-permuted gru_w_ih
__device__ float g_wkvT [256*384];              // [attn_wk|attn_wv]^T (tf32, K-perm)
__device__ float g_wq2  [128*640];              // outfn_w @ out_proj_w
__device__ float g_w3t  [128*640];              // fused qh weight (tf32, K-perm)
__device__ float g_bqh  [128];                  // fused qh bias

__device__ __forceinline__ uint32_t f2tf(float x) {
    uint32_t u; asm("cvt.rna.tf32.f32 %0, %1;" : "=r"(u) : "f"(x)); return u;
}
__device__ __forceinline__ float tfr(float x) { return __uint_as_float(f2tf(x)); }

__device__ __forceinline__ void cp16(uint32_t dst, const void* src) {
    asm volatile("cp.async.cg.shared.global [%0], [%1], 16;" :: "r"(dst), "l"(src));
}

// ---------------- TF32 mma.sync GEMM, TN form, K-interleaved operands -------
// C[M,N] = A[M,K] * B[N,K]^T + bias.  M%128==0, N%128==0, K%16==0, K>=32.
// grid = (N/128, M/128), 256 threads, 8 warps of 32x64, 3-stage cp.async.
__global__ __launch_bounds__(256, 2)
void tgemm(int K, const float* __restrict__ A, int lda,
           const float* __restrict__ B,
           float* __restrict__ C, int ldc,
           const float* __restrict__ bias)
{
    __shared__ float As[3][128][16];
    __shared__ float Bs[3][128][16];
    int tid = threadIdx.x;
    int warp = tid >> 5, lane = tid & 31;
    int row0 = blockIdx.y * 128, col0 = blockIdx.x * 128;
    int m0 = (warp >> 1) * 32, n0 = (warp & 1) * 64;
    int g = lane >> 2, t = lane & 3;

    float c[2][8][4];
#pragma unroll
    for (int mi = 0; mi < 2; mi++)
#pragma unroll
        for (int ni = 0; ni < 8; ni++)
#pragma unroll
            for (int i = 0; i < 4; i++) c[mi][ni][i] = 0.f;

    const float* Ap = A + (size_t)row0 * lda;
    const float* Bp = B + (size_t)col0 * K;

    uint32_t sA = (uint32_t)__cvta_generic_to_shared(&As[0][0][0]);
    uint32_t sB = (uint32_t)__cvta_generic_to_shared(&Bs[0][0][0]);
    const uint32_t stg = 128u*16u*4u;

#define LOADSTAGE(s, kt) {                                                    \
        _Pragma("unroll")                                                     \
        for (int i = 0; i < 2; i++) {                                         \
            int j = tid + i*256, r = j >> 2, q = j & 3;                       \
            cp16(sA + (uint32_t)(s)*stg + (uint32_t)(r*16 + q*4)*4u,          \
                 Ap + (size_t)r*lda + (kt)*16 + q*4);                         \
            cp16(sB + (uint32_t)(s)*stg + (uint32_t)(r*16 + q*4)*4u,          \
                 Bp + (size_t)r*K + (kt)*16 + q*4);                           \
        }                                                                     \
        asm volatile("cp.async.commit_group;" ::: "memory");                  \
    }

    int T = K >> 4;            // >= 24 for all call sites
    LOADSTAGE(0, 0);
    LOADSTAGE(1, 1);

    int s = 0, sw = 2;
    for (int kt = 0; kt < T; kt++) {
        if (kt + 1 < T) asm volatile("cp.async.wait_group 1;" ::: "memory");
        else            asm volatile("cp.async.wait_group 0;" ::: "memory");
        __syncthreads();
        if (kt + 2 < T) LOADSTAGE(sw, kt + 2);

        float4 av[2][2], bv[8];
#pragma unroll
        for (int mi = 0; mi < 2; mi++) {
            int rm = m0 + mi*16 + g;
            av[mi][0] = *(const float4*)&As[s][rm    ][t*4];
            av[mi][1] = *(const float4*)&As[s][rm + 8][t*4];
        }
#pragma unroll
        for (int ni = 0; ni < 8; ni++) {
            int cn = n0 + ni*8 + g;
            bv[ni] = *(const float4*)&Bs[s][cn][t*4];
        }
#pragma unroll
        for (int mi = 0; mi < 2; mi++)
#pragma unroll
            for (int ni = 0; ni < 8; ni++) {
                asm volatile(
                    "mma.sync.aligned.m16n8k8.row.col.f32.tf32.tf32.f32 "
                    "{%0,%1,%2,%3},{%4,%5,%6,%7},{%8,%9},{%0,%1,%2,%3};\n"
                    : "+f"(c[mi][ni][0]), "+f"(c[mi][ni][1]),
                      "+f"(c[mi][ni][2]), "+f"(c[mi][ni][3])
                    : "r"(__float_as_uint(av[mi][0].x)), "r"(__float_as_uint(av[mi][1].x)),
                      "r"(__float_as_uint(av[mi][0].y)), "r"(__float_as_uint(av[mi][1].y)),
                      "r"(__float_as_uint(bv[ni].x)),    "r"(__float_as_uint(bv[ni].y)));
                asm volatile(
                    "mma.sync.aligned.m16n8k8.row.col.f32.tf32.tf32.f32 "
                    "{%0,%1,%2,%3},{%4,%5,%6,%7},{%8,%9},{%0,%1,%2,%3};\n"
                    : "+f"(c[mi][ni][0]), "+f"(c[mi][ni][1]),
                      "+f"(c[mi][ni][2]), "+f"(c[mi][ni][3])
                    : "r"(__float_as_uint(av[mi][0].z)), "r"(__float_as_uint(av[mi][1].z)),
                      "r"(__float_as_uint(av[mi][0].w)), "r"(__float_as_uint(av[mi][1].w)),
                      "r"(__float_as_uint(bv[ni].z)),    "r"(__float_as_uint(bv[ni].w)));
            }
        __syncthreads();
        s  = (s  == 2) ? 0 : s  + 1;
        sw = (sw == 2) ? 0 : sw + 1;
    }

#pragma unroll
    for (int mi = 0; mi < 2; mi++) {
        size_t r1 = (size_t)(row0 + m0 + mi*16 + g);
        size_t r2 = r1 + 8;
#pragma unroll
        for (int ni = 0; ni < 8; ni++) {
            int cc = col0 + n0 + ni*8 + 2*t;
            float b0 = 0.f, b1 = 0.f;
            if (bias) { b0 = bias[cc]; b1 = bias[cc + 1]; }
            *(float2*)&C[r1*ldc + cc] = make_float2(c[mi][ni][0] + b0, c[mi][ni][1] + b1);
            *(float2*)&C[r2*ldc + cc] = make_float2(c[mi][ni][2] + b0, c[mi][ni][3] + b1);
        }
    }
#undef LOADSTAGE
}

// ---------------- build full_vals, nb, last_event_feat (tf32 + K-perm) -----
__global__ void build_kernel(const int* __restrict__ nids,
                             const int* __restrict__ hist_nids,
                             const int* __restrict__ aids,
                             const int* __restrict__ eids,
                             const float* __restrict__ hist_ts,
                             const int* __restrict__ dirs,
                             const float* __restrict__ node_feat,
                             const float* __restrict__ edge_feat,
                             const float* __restrict__ anony,
                             const float* __restrict__ tw,
                             const float* __restrict__ tb)
{
    int bl = blockIdx.x;            // b*HL + l
    int b  = bl / HL, l = bl % HL;
    int j  = threadIdx.x;           // 0..127
    int jp = PERM(j);
    int hn  = hist_nids[bl];
    int dir = dirs[bl];
    int nid = nids[b];
    int src = dir ? nid : hn;
    int dst = dir ? hn  : nid;
    float sv = tfr(node_feat[(size_t)src*NF + j]);
    float dv = tfr(node_feat[(size_t)dst*NF + j]);
    float av = tfr(anony[(size_t)aids[bl]*NF + j]);
    float ev = tfr(edge_feat[(size_t)eids[bl]*EF + j]);
    float dt = hist_ts[b*HL + HL-1] - hist_ts[bl];
    float tv = tfr(cosf(dt*tw[j] + tb[j]));

    float* fv = g_full + (size_t)bl*DM;
    if (l == HL-1) {
        float* lef = g_lef + (size_t)b*DIN;
        lef[jp] = sv; lef[NF+jp] = dv; lef[2*NF+jp] = av; lef[3*NF+jp] = ev;
        fv[jp] = 0.f; fv[NF+jp] = 0.f; fv[2*NF+jp] = 0.f; fv[3*NF+jp] = 0.f;
        fv[4*NF+jp] = tv;
    } else {
        fv[jp] = sv; fv[NF+jp] = dv; fv[2*NF+jp] = av; fv[3*NF+jp] = ev;
        fv[4*NF+jp] = tv;
    }
    float* nb = g_nb + (size_t)bl*384;
    nb[jp]        = tfr(node_feat[(size_t)hn*NF + j]);
    nb[NF + jp]   = ev;
    nb[2*NF + jp] = tv;
}

__global__ void transpose_odew(const float* __restrict__ w)
{
    int idx = blockIdx.x*128 + threadIdx.x;
    int j = idx >> 7, k = idx & 127;
    g_odewT[k*NF + j] = w[idx];
}

__global__ void pack_wkvT(const float* __restrict__ wk, const float* __restrict__ wv)
{
    int idx = blockIdx.x*128 + threadIdx.x;   // 384*128
    int k = idx >> 7, n = idx & 127;
    int kp = PERM(k);
    g_wkvT[(size_t)n*384 + kp]         = tfr(wk[idx]);
    g_wkvT[(size_t)(128 + n)*384 + kp] = tfr(wv[idx]);
}

// tf32-round + K-permute columns of a row-major [rows, K] matrix
__global__ void cvt_tf32p(const float* __restrict__ s, float* __restrict__ d,
                          int K, int n)
{
    int i = blockIdx.x*256 + threadIdx.x;
    if (i < n) {
        int row = i / K, col = i % K;
        d[(size_t)row*K + PERM(col)] = tfr(s[i]);
    }
}

// W3 precompute: Wq2 = outfn_w @ out_proj_w  ([128,640])
__global__ void w3_step1(const float* __restrict__ outfn_w, const float* __restrict__ opw)
{
    __shared__ float srow[8][640];
    int i0 = blockIdx.x * 8;    // grid 16
    for (int j = threadIdx.x; j < 8*640; j += 128)
        srow[j/640][j%640] = outfn_w[(size_t)(i0 + j/640)*640 + (j%640)];
    __syncthreads();
    for (int t = 0; t < 5; t++) {
        int d = threadIdx.x + t*128;
        float acc[8] = {0,0,0,0,0,0,0,0};
        for (int k = 0; k < 640; k++) {
            float w = opw[(size_t)k*640 + d];
#pragma unroll
            for (int r = 0; r < 8; r++) acc[r] += srow[r][k]*w;
        }
        for (int r = 0; r < 8; r++) g_wq2[(size_t)(i0+r)*640 + d] = acc[r];
    }
}
// W3t[j,PERM(d)] = sum_i Wq2[i,d] * attn_wq[i,j]
__global__ void w3_step2(const float* __restrict__ attn_wq)
{
    __shared__ float wqc[8][128];
    int j0 = blockIdx.x * 8;    // grid 16
    for (int idx = threadIdx.x; idx < 8*128; idx += 128) {
        int r = idx >> 7, i = idx & 127;
        wqc[r][i] = attn_wq[(size_t)i*128 + j0 + r];
    }
    __syncthreads();
    for (int t = 0; t < 5; t++) {
        int d = threadIdx.x + t*128;
        int dp = PERM(d);
        float acc[8] = {0,0,0,0,0,0,0,0};
        for (int i = 0; i < 128; i++) {
            float w = g_wq2[(size_t)i*640 + d];
#pragma unroll
            for (int r = 0; r < 8; r++) acc[r] += wqc[r][i]*w;
        }
        for (int r = 0; r < 8; r++) g_w3t[(size_t)(j0+r)*640 + dp] = tfr(acc[r]);
    }
}
// bqh[j] = sum_i (outfn_b[i] + sum_k out_proj_b[k]*outfn_w[i,k]) * attn_wq[i,j]
__global__ void w3_bias(const float* __restrict__ opb, const float* __restrict__ outfn_w,
                        const float* __restrict__ outfn_b, const float* __restrict__ attn_wq)
{
    __shared__ float bq2[128];
    int i = threadIdx.x;
    float a = outfn_b[i];
    for (int k = 0; k < 640; k++) a += opb[k]*outfn_w[(size_t)i*640 + k];
    bq2[i] = a;
    __syncthreads();
    float s = 0.f;
    for (int ii = 0; ii < 128; ii++) s += bq2[ii]*attn_wq[(size_t)ii*128 + i];
    g_bqh[i] = s;
}

// ---------------- attention 1 (query = last position) ----------------------
__global__ void attn1_kernel(const int* __restrict__ hist_nids)
{
    int b = blockIdx.x, tid = threadIdx.x;   // 256 threads
    __shared__ float sq[DM];
    __shared__ float sS[NHEAD*HL];
    __shared__ float sA[NHEAD*HL];
    for (int d = tid; d < DM; d += 256) sq[d] = g_qlast[(size_t)b*DM + d];
    __syncthreads();

    int warp = tid >> 5, lane = tid & 31;
    for (int p = warp; p < NHEAD*HL; p += 8) {
        int h = p / HL, m = p % HL;
        const float* krow = g_kv + (size_t)(b*HL + m)*1280 + h*DH;
        const float* qrow = sq + h*DH;
        float s = 0.f;
#pragma unroll
        for (int i = 0; i < 10; i++) { int d = lane + i*32; s += qrow[d]*krow[d]; }
#pragma unroll
        for (int o = 16; o; o >>= 1) s += __shfl_xor_sync(0xffffffffu, s, o);
        if (!lane) sS[p] = s * 0.05590169943749474f;   // 1/sqrt(320)
    }
    __syncthreads();
    if (tid < NHEAD) {
        int h = tid;
        float sc[HL], mx = -1e30f;
        for (int m = 0; m < HL; m++) {
            float v = sS[h*HL + m];
            if (hist_nids[b*HL + m] == 0 && m != HL-1) v = -1e9f;
            sc[m] = v; mx = fmaxf(mx, v);
        }
        float sum = 0.f;
        for (int m = 0; m < HL; m++) { float e = expf(sc[m]-mx); sc[m] = e; sum += e; }
        float inv = 1.f/sum;
        for (int m = 0; m < HL; m++) sA[h*HL + m] = sc[m]*inv;
    }
    __syncthreads();
    for (int d = tid; d < DM; d += 256) {
        int h = d / DH;
        const float* vbase = g_kv + (size_t)b*HL*1280 + 640 + d;
        float accv = 0.f;
#pragma unroll
        for (int m = 0; m < HL; m++) accv += sA[h*HL + m] * vbase[(size_t)m*1280];
        g_ctx[(size_t)b*DM + PERM(d)] = tfr(accv);   // K-permuted: feeds qh GEMM
    }
}

// ---------------- attention 2 + merge + GRU ---------------------------------
__global__ void attn2_gru_kernel(const int* __restrict__ nids,
                                 const int* __restrict__ hist_nids,
                                 const float* __restrict__ hist_ts,
                                 const float* __restrict__ node_feat,
                                 const float* __restrict__ merge_w,
                                 const float* __restrict__ merge_b,
                                 const float* __restrict__ gwhh,
                                 const float* __restrict__ gbhh,
                                 float* __restrict__ out)
{
    int b = blockIdx.x, tid = threadIdx.x;   // 128 threads
    __shared__ float sqh[NF], ssc[HL], sa[HL], scat[2*NF], shpl[NF];
    sqh[tid] = g_qh[(size_t)b*NF + tid];
    __syncthreads();
    int warp = tid >> 5, lane = tid & 31;
    for (int l = warp; l < HL; l += 4) {
        const float* kr = g_khv + (size_t)(b*HL + l)*256;
        float s = 0.f;
#pragma unroll
        for (int i = 0; i < 4; i++) { int d = lane + i*32; s += sqh[d]*kr[d]; }
#pragma unroll
        for (int o = 16; o; o >>= 1) s += __shfl_xor_sync(0xffffffffu, s, o);
        if (!lane) ssc[l] = s * 0.08838834764831845f;  // 1/sqrt(128)
    }
    __syncthreads();
    if (tid == 0) {
        float sc[HL], mx = -1e30f;
        for (int l = 0; l < HL; l++) {
            float v = ssc[l];
            if (hist_nids[b*HL + l] == 0 && l != HL-1) v = -1e9f;
            sc[l] = v; mx = fmaxf(mx, v);
        }
        float sum = 0.f;
        for (int l = 0; l < HL; l++) { float e = expf(sc[l]-mx); sc[l] = e; sum += e; }
        float inv = 1.f/sum;
        for (int l = 0; l < HL; l++) sa[l] = sc[l]*inv;
    }
    __syncthreads();
    float c2 = 0.f;
#pragma unroll
    for (int l = 0; l < HL; l++) c2 += sa[l] * g_khv[(size_t)(b*HL + l)*256 + 128 + tid];
    scat[tid]      = c2;
    scat[NF + tid] = node_feat[(size_t)nids[b]*NF + tid];
    __syncthreads();

    float acc = merge_b[tid];
#pragma unroll 8
    for (int k = 0; k < 2*NF; k++) acc = fmaf(scat[k], merge_w[k*NF + tid], acc);
    float hpl = tanhf(acc);
    shpl[tid] = hpl;
    __syncthreads();

    float gh[3];
#pragma unroll
    for (int c = 0; c < 3; c++) {
        int i = c*NF + tid;
        float a = gbhh[i];
        const float* wrow = gwhh + (size_t)i*NF;
#pragma unroll 8
        for (int k = 0; k < NF; k++) a = fmaf(shpl[k], wrow[k], a);
        gh[c] = a;
    }
    const float* gi = g_gi + (size_t)b*384;
    float r = 1.f/(1.f + expf(-(gi[tid]       + gh[0])));
    float z = 1.f/(1.f + expf(-(gi[NF + tid]  + gh[1])));
    float n = tanhf(gi[2*NF + tid] + r*gh[2]);
    float hpr = (1.f - z)*n + z*hpl;
    g_hpr[(size_t)b*NF + tid] = hpr;
    out[(size_t)BS*NF + (size_t)b*NF + tid] = hpr;        // h_right
    if (tid == 0) out[(size_t)2*BS*NF + b] = hist_ts[b*HL + HL-1];
}

// ---------------- ODE (RK4, 8 steps), 8 samples/block, weights in smem ------
__global__ __launch_bounds__(128)
void ode_kernel(const float* __restrict__ hist_ts,
                const float* __restrict__ tnw,
                const float* __restrict__ tnb,
                const float* __restrict__ odeb,
                float* __restrict__ out)
{
    extern __shared__ float sm[];           // wsm[16384] + ysm[128*8]
    float* wsm = sm;
    float* ysm = sm + NF*NF;
    int j = threadIdx.x;
    int b0 = blockIdx.x * 8;

    for (int i = j; i < NF*NF; i += 128) wsm[i] = g_odewT[i];
    float tw = tnw[j], tb = tnb[j], ob = odeb[j];
    float t0v[8], rat[8], z[8];
#pragma unroll
    for (int s = 0; s < 8; s++) {
        float a = hist_ts[(b0+s)*HL + HL-2];
        float b = hist_ts[(b0+s)*HL + HL-1];
        t0v[s] = a; rat[s] = b - a;
        z[s] = g_hpr[(size_t)(b0+s)*NF + j];
    }
    __syncthreads();
    const float ds = 1.f/ODE_STEPS;

    auto fstage = [&](float sfrac, const float* zi, float* f) {
        __syncthreads();   // WAR: previous reads of ysm done
#pragma unroll
        for (int s = 0; s < 8; s++) {
            float te = __cosf((sfrac*rat[s] + t0v[s])*tw + tb);
            ysm[j*8 + s] = zi[s] + te;
        }
        __syncthreads();
        float acc[8];
#pragma unroll
        for (int s = 0; s < 8; s++) acc[s] = ob;
#pragma unroll 4
        for (int k = 0; k < NF; k++) {
            float w = wsm[k*NF + j];
            float4 y0 = *(const float4*)&ysm[k*8];
            float4 y1 = *(const float4*)&ysm[k*8 + 4];
            acc[0] = fmaf(y0.x, w, acc[0]);
            acc[1] = fmaf(y0.y, w, acc[1]);
            acc[2] = fmaf(y0.z, w, acc[2]);
            acc[3] = fmaf(y0.w, w, acc[3]);
            acc[4] = fmaf(y1.x, w, acc[4]);
            acc[5] = fmaf(y1.y, w, acc[5]);
            acc[6] = fmaf(y1.z, w, acc[6]);
            acc[7] = fmaf(y1.w, w, acc[7]);
        }
#pragma unroll
        for (int s = 0; s < 8; s++) {
            float th;
            asm("tanh.approx.f32 %0, %1;" : "=f"(th) : "f"(acc[s]));
            f[s] = th * rat[s];
        }
    };

    for (int i = 0; i < ODE_STEPS; i++) {
        float s0 = i * ds;
        float k1[8], k2[8], k3[8], k4[8], zi[8];
        fstage(s0, z, k1);
#pragma unroll
        for (int s = 0; s < 8; s++) zi[s] = z[s] + 0.5f*ds*k1[s];
        fstage(s0 + 0.5f*ds, zi, k2);
#pragma unroll
        for (int s = 0; s < 8; s++) zi[s] = z[s] + 0.5f*ds*k2[s];
        fstage(s0 + 0.5f*ds, zi, k3);
#pragma unroll
        for (int s = 0; s < 8; s++) zi[s] = z[s] + ds*k3[s];
        fstage(s0 + ds, zi, k4);
#pragma unroll
        for (int s = 0; s < 8; s++)
            z[s] += ds/6.f * (k1[s] + 2.f*k2[s] + 2.f*k3[s] + k4[s]);
    }
#pragma unroll
    for (int s = 0; s < 8; s++)
        out[(size_t)(b0+s)*NF + j] = z[s];   // h_left
}

// ---------------- host ------------------------------------------------------
extern "C" void kernel_launch(void* const* d_in, const int* in_sizes, int n_in,
                              void* d_out, int out_size)
{
    const int*   nids       = (const int*)  d_in[0];
    const int*   hist_nids  = (const int*)  d_in[2];
    const int*   aids       = (const int*)  d_in[3];
    const int*   eids       = (const int*)  d_in[4];
    const float* hist_ts    = (const float*)d_in[5];
    const int*   dirs       = (const int*)  d_in[6];
    const float* node_feat  = (const float*)d_in[7];
    const float* edge_feat  = (const float*)d_in[8];
    const float* anony_emb  = (const float*)d_in[9];
    const float* time_w     = (const float*)d_in[10];
    const float* time_b     = (const float*)d_in[11];
    const float* in_proj_w  = (const float*)d_in[12];
    const float* in_proj_b  = (const float*)d_in[13];
    const float* out_proj_w = (const float*)d_in[14];
    const float* out_proj_b = (const float*)d_in[15];
    const float* outfn_w    = (const float*)d_in[16];
    const float* outfn_b    = (const float*)d_in[17];
    const float* attn_wq    = (const float*)d_in[18];
    const float* attn_wk    = (const float*)d_in[19];
    const float* attn_wv    = (const float*)d_in[20];
    const float* merge_w    = (const float*)d_in[21];
    const float* merge_b    = (const float*)d_in[22];
    const float* gru_w_ih   = (const float*)d_in[23];
    const float* gru_w_hh   = (const float*)d_in[24];
    const float* gru_b_ih   = (const float*)d_in[25];
    const float* gru_b_hh   = (const float*)d_in[26];
    const float* ode_w      = (const float*)d_in[27];
    const float* ode_b      = (const float*)d_in[28];
    const float* tnode_w    = (const float*)d_in[29];
    const float* tnode_b    = (const float*)d_in[30];

    float* out = (float*)d_out;

    float *p_full, *p_kv, *p_lef, *p_qlast, *p_ctx, *p_qh, *p_khv, *p_nb,
          *p_gi, *p_ipw, *p_gwih, *p_wkvT, *p_w3t, *p_bqh;
    cudaGetSymbolAddress((void**)&p_full,  g_full);
    cudaGetSymbolAddress((void**)&p_kv,    g_kv);
    cudaGetSymbolAddress((void**)&p_lef,   g_lef);
    cudaGetSymbolAddress((void**)&p_qlast, g_qlast);
    cudaGetSymbolAddress((void**)&p_ctx,   g_ctx);
    cudaGetSymbolAddress((void**)&p_qh,    g_qh);
    cudaGetSymbolAddress((void**)&p_khv,   g_khv);
    cudaGetSymbolAddress((void**)&p_nb,    g_nb);
    cudaGetSymbolAddress((void**)&p_gi,    g_gi);
    cudaGetSymbolAddress((void**)&p_ipw,   g_ipw);
    cudaGetSymbolAddress((void**)&p_gwih,  g_gwih);
    cudaGetSymbolAddress((void**)&p_wkvT,  g_wkvT);
    cudaGetSymbolAddress((void**)&p_w3t,   g_w3t);
    cudaGetSymbolAddress((void**)&p_bqh,   g_bqh);

    // ODE needs 69.6KB dynamic smem (> 48KB default): opt in (idempotent)
    cudaFuncSetAttribute(ode_kernel, cudaFuncAttributeMaxDynamicSharedMemorySize,
                         (NF*NF + NF*8) * 4);

    // --- prep (gather, packing, weight conversion, W3 fusion precompute) ---
    build_kernel<<<BS*HL, 128>>>(nids, hist_nids, aids, eids, hist_ts, dirs,
                                 node_feat, edge_feat, anony_emb, time_w, time_b);
    transpose_odew<<<128, 128>>>(ode_w);
    pack_wkvT<<<384, 128>>>(attn_wk, attn_wv);
    cvt_tf32p<<<(1920*640 + 255)/256, 256>>>(in_proj_w, p_ipw, 640, 1920*640);
    cvt_tf32p<<<(384*512 + 255)/256, 256>>>(gru_w_ih, p_gwih, 512, 384*512);
    w3_step1<<<16, 128>>>(outfn_w, out_proj_w);
    w3_step2<<<16, 128>>>(attn_wq);
    w3_bias<<<1, 128>>>(out_proj_b, outfn_w, outfn_b, attn_wq);

    // --- KV projection: [81920,640] x [1280,640]^T ---
    tgemm<<<dim3(10, 640), 256>>>(DM, p_full, DM, p_ipw + (size_t)DM*DM,
                                  p_kv, 1280, in_proj_b + DM);

    // --- Q at last position: [4096,640] x [640,640]^T ---
    tgemm<<<dim3(5, 32), 256>>>(DM, p_full + (size_t)(HL-1)*DM, HL*DM,
                                p_ipw, p_qlast, DM, in_proj_b);

    // --- gi = lef @ gru_w_ih^T: [4096,512] x [384,512]^T ---
    tgemm<<<dim3(3, 32), 256>>>(DIN, p_lef, DIN, p_gwih, p_gi, 384, gru_b_ih);

    // --- kh|vh = nb @ wkvT^T: [81920,384] x [256,384]^T ---
    tgemm<<<dim3(2, 640), 256>>>(384, p_nb, 384, p_wkvT, p_khv, 256,
                                 (const float*)nullptr);

    // --- attention 1 -> ctx ---
    attn1_kernel<<<BS, 256>>>(hist_nids);

    // --- fused qh = ctx @ W3t^T: [4096,640] x [128,640]^T ---
    tgemm<<<dim3(1, 32), 256>>>(DM, p_ctx, DM, p_w3t, p_qh, NF, p_bqh);

    // --- attention 2 + merge + GRU (writes h_right + ts) ---
    attn2_gru_kernel<<<BS, 128>>>(nids, hist_nids, hist_ts, node_feat,
                                  merge_w, merge_b, gru_w_hh, gru_b_hh, out);

    // --- ODE RK4 (writes h_left) ---
    ode_kernel<<<BS/8, 128, (NF*NF + NF*8)*4>>>(hist_ts, tnode_w, tnode_b,
                                                ode_b, out);
}

// round 8
// speedup vs baseline: 1.0467x; 1.0467x over previous
#include <cuda_runtime.h>
#include <cuda_bf16.h>
#include <math.h>
#include <stdint.h>

// Problem constants
#define BS 4096
#define HL 20
#define NF 128
#define EF 128
#define TF 128
#define DM 640          // 3*NF + EF + TF
#define DIN 512         // DM - TF
#define NHEAD 2
#define DH 320          // DM / NHEAD
#define ODE_STEPS 8

// K-block interleave (4x4 transpose within each 16-block; self-inverse).
#define PERM(k) (((k) & ~15) | (((k) & 3) << 2) | (((k) & 15) >> 2))

// ---------------- scratch (device globals; no allocation allowed) ----------
__device__ float g_full [(size_t)BS*HL*DM];     // full_vals (tf32, PERM space)
__device__ float g_nb   [(size_t)BS*HL*384];    // nb (tf32, PERM space)
__device__ float g_lef  [(size_t)BS*DIN];       // last_event_feat (tf32, PERM)
__device__ float g_u1   [(size_t)BS*1280];      // u1 (normal cols)
__device__ float g_s    [(size_t)BS*1280];      // weighted sums (tf32, PERM)
__device__ float g_qh   [(size_t)BS*NF];        // qh (tf32, PERM via PERMOUT)
__device__ float g_u2   [(size_t)BS*384];       // u2 (tf32, PERM via PERMOUT)
__device__ float g_gi   [(size_t)BS*384];
__device__ float g_hpr  [(size_t)BS*NF];
__device__ float g_odewT[NF*NF];
__device__ float g_gwih [384*512];              // tf32+PERM gru_w_ih
__device__ float g_wu   [1280*640];             // WU (tf32, K-PERM)
__device__ float g_cu   [1280];                 // u1 bias
__device__ float g_wq2  [128*640];              // outfn_w @ out_proj_w (fp32)
__device__ float g_w3   [128*640];              // attn_wq^T outfn out_proj (fp32)
__device__ float g_bqh  [128];
__device__ float g_w4   [128*1280];             // W3 folded with Wv (tf32, K-PERM)
__device__ float g_b4   [128];
__device__ float g_wk2  [384*128];              // attn_wk (tf32, K-PERM)
__device__ float g_wm2p [384*128];              // attn_wv @ merge_w_top, rows PERM

__device__ __forceinline__ uint32_t f2tf(float x) {
    uint32_t u; asm("cvt.rna.tf32.f32 %0, %1;" : "=r"(u) : "f"(x)); return u;
}
__device__ __forceinline__ float tfr(float x) { return __uint_as_float(f2tf(x)); }

__device__ __forceinline__ void cp16(uint32_t dst, const void* src) {
    asm volatile("cp.async.cg.shared.global [%0], [%1], 16;" :: "r"(dst), "l"(src));
}

// ---------------- TF32 mma.sync GEMM, TN form, K-interleaved operands -------
// C[M,N] = A[M,K] * B[N,K]^T + bias.  M%128==0, N%128==0, K%16==0, K>=32.
// PERMOUT: store C with PERM'd (tf32-rounded) columns so it can feed A of a
// later GEMM / PERM-space dot.
template<bool PERMOUT>
__global__ __launch_bounds__(256, 2)
void tgemm(int K, const float* __restrict__ A, int lda,
           const float* __restrict__ B,
           float* __restrict__ C, int ldc,
           const float* __restrict__ bias)
{
    __shared__ float As[3][128][16];
    __shared__ float Bs[3][128][16];
    int tid = threadIdx.x;
    int warp = tid >> 5, lane = tid & 31;
    int row0 = blockIdx.y * 128, col0 = blockIdx.x * 128;
    int m0 = (warp >> 1) * 32, n0 = (warp & 1) * 64;
    int g = lane >> 2, t = lane & 3;

    float c[2][8][4];
#pragma unroll
    for (int mi = 0; mi < 2; mi++)
#pragma unroll
        for (int ni = 0; ni < 8; ni++)
#pragma unroll
            for (int i = 0; i < 4; i++) c[mi][ni][i] = 0.f;

    const float* Ap = A + (size_t)row0 * lda;
    const float* Bp = B + (size_t)col0 * K;

    uint32_t sA = (uint32_t)__cvta_generic_to_shared(&As[0][0][0]);
    uint32_t sB = (uint32_t)__cvta_generic_to_shared(&Bs[0][0][0]);
    const uint32_t stg = 128u*16u*4u;

#define LOADSTAGE(s, kt) {                                                    \
        _Pragma("unroll")                                                     \
        for (int i = 0; i < 2; i++) {                                         \
            int j = tid + i*256, r = j >> 2, q = j & 3;                       \
            cp16(sA + (uint32_t)(s)*stg + (uint32_t)(r*16 + q*4)*4u,          \
                 Ap + (size_t)r*lda + (kt)*16 + q*4);                         \
            cp16(sB + (uint32_t)(s)*stg + (uint32_t)(r*16 + q*4)*4u,          \
                 Bp + (size_t)r*K + (kt)*16 + q*4);                           \
        }                                                                     \
        asm volatile("cp.async.commit_group;" ::: "memory");                  \
    }

    int T = K >> 4;            // >= 2 for all call sites
    LOADSTAGE(0, 0);
    LOADSTAGE(1, 1);

    int s = 0, sw = 2;
    for (int kt = 0; kt < T; kt++) {
        if (kt + 1 < T) asm volatile("cp.async.wait_group 1;" ::: "memory");
        else            asm volatile("cp.async.wait_group 0;" ::: "memory");
        __syncthreads();
        if (kt + 2 < T) LOADSTAGE(sw, kt + 2);

        float4 av[2][2], bv[8];
#pragma unroll
        for (int mi = 0; mi < 2; mi++) {
            int rm = m0 + mi*16 + g;
            av[mi][0] = *(const float4*)&As[s][rm    ][t*4];
            av[mi][1] = *(const float4*)&As[s][rm + 8][t*4];
        }
#pragma unroll
        for (int ni = 0; ni < 8; ni++) {
            int cn = n0 + ni*8 + g;
            bv[ni] = *(const float4*)&Bs[s][cn][t*4];
        }
#pragma unroll
        for (int mi = 0; mi < 2; mi++)
#pragma unroll
            for (int ni = 0; ni < 8; ni++) {
                asm volatile(
                    "mma.sync.aligned.m16n8k8.row.col.f32.tf32.tf32.f32 "
                    "{%0,%1,%2,%3},{%4,%5,%6,%7},{%8,%9},{%0,%1,%2,%3};\n"
                    : "+f"(c[mi][ni][0]), "+f"(c[mi][ni][1]),
                      "+f"(c[mi][ni][2]), "+f"(c[mi][ni][3])
                    : "r"(__float_as_uint(av[mi][0].x)), "r"(__float_as_uint(av[mi][1].x)),
                      "r"(__float_as_uint(av[mi][0].y)), "r"(__float_as_uint(av[mi][1].y)),
                      "r"(__float_as_uint(bv[ni].x)),    "r"(__float_as_uint(bv[ni].y)));
                asm volatile(
                    "mma.sync.aligned.m16n8k8.row.col.f32.tf32.tf32.f32 "
                    "{%0,%1,%2,%3},{%4,%5,%6,%7},{%8,%9},{%0,%1,%2,%3};\n"
                    : "+f"(c[mi][ni][0]), "+f"(c[mi][ni][1]),
                      "+f"(c[mi][ni][2]), "+f"(c[mi][ni][3])
                    : "r"(__float_as_uint(av[mi][0].z)), "r"(__float_as_uint(av[mi][1].z)),
                      "r"(__float_as_uint(av[mi][0].w)), "r"(__float_as_uint(av[mi][1].w)),
                      "r"(__float_as_uint(bv[ni].z)),    "r"(__float_as_uint(bv[ni].w)));
            }
        __syncthreads();
        s  = (s  == 2) ? 0 : s  + 1;
        sw = (sw == 2) ? 0 : sw + 1;
    }

#pragma unroll
    for (int mi = 0; mi < 2; mi++) {
        size_t r1 = (size_t)(row0 + m0 + mi*16 + g);
        size_t r2 = r1 + 8;
#pragma unroll
        for (int ni = 0; ni < 8; ni++) {
            int cc = col0 + n0 + ni*8 + 2*t;
            float b0 = 0.f, b1 = 0.f;
            if (bias) { b0 = bias[cc]; b1 = bias[cc + 1]; }
            float v0 = c[mi][ni][0] + b0, v1 = c[mi][ni][1] + b1;
            float v2 = c[mi][ni][2] + b0, v3 = c[mi][ni][3] + b1;
            if (PERMOUT) {
                int p0 = PERM(cc), p1 = PERM(cc + 1);
                C[r1*ldc + p0] = tfr(v0); C[r1*ldc + p1] = tfr(v1);
                C[r2*ldc + p0] = tfr(v2); C[r2*ldc + p1] = tfr(v3);
            } else {
                *(float2*)&C[r1*ldc + cc] = make_float2(v0, v1);
                *(float2*)&C[r2*ldc + cc] = make_float2(v2, v3);
            }
        }
    }
#undef LOADSTAGE
}

// ---------------- build full_vals, nb, last_event_feat (tf32 + PERM) -------
__global__ void build_kernel(const int* __restrict__ nids,
                             const int* __restrict__ hist_nids,
                             const int* __restrict__ aids,
                             const int* __restrict__ eids,
                             const float* __restrict__ hist_ts,
                             const int* __restrict__ dirs,
                             const float* __restrict__ node_feat,
                             const float* __restrict__ edge_feat,
                             const float* __restrict__ anony,
                             const float* __restrict__ tw,
                             const float* __restrict__ tb)
{
    int bl = blockIdx.x;            // b*HL + l
    int b  = bl / HL, l = bl % HL;
    int j  = threadIdx.x;           // 0..127
    int jp = PERM(j);
    int hn  = hist_nids[bl];
    int dir = dirs[bl];
    int nid = nids[b];
    int src = dir ? nid : hn;
    int dst = dir ? hn  : nid;
    float sv = tfr(node_feat[(size_t)src*NF + j]);
    float dv = tfr(node_feat[(size_t)dst*NF + j]);
    float av = tfr(anony[(size_t)aids[bl]*NF + j]);
    float ev = tfr(edge_feat[(size_t)eids[bl]*EF + j]);
    float dt = hist_ts[b*HL + HL-1] - hist_ts[bl];
    float tv = tfr(cosf(dt*tw[j] + tb[j]));

    float* fv = g_full + (size_t)bl*DM;
    if (l == HL-1) {
        float* lef = g_lef + (size_t)b*DIN;
        lef[jp] = sv; lef[NF+jp] = dv; lef[2*NF+jp] = av; lef[3*NF+jp] = ev;
        fv[jp] = 0.f; fv[NF+jp] = 0.f; fv[2*NF+jp] = 0.f; fv[3*NF+jp] = 0.f;
        fv[4*NF+jp] = tv;
    } else {
        fv[jp] = sv; fv[NF+jp] = dv; fv[2*NF+jp] = av; fv[3*NF+jp] = ev;
        fv[4*NF+jp] = tv;
    }
    float* nb = g_nb + (size_t)bl*384;
    nb[jp]        = tfr(node_feat[(size_t)hn*NF + j]);
    nb[NF + jp]   = ev;
    nb[2*NF + jp] = tv;
}

__global__ void transpose_odew(const float* __restrict__ w)
{
    int idx = blockIdx.x*128 + threadIdx.x;
    int j = idx >> 7, k = idx & 127;
    g_odewT[k*NF + j] = w[idx];
}

// tf32-round + K-permute columns of a row-major [rows, K] matrix
__global__ void cvt_tf32p(const float* __restrict__ s, float* __restrict__ d,
                          int K, int n)
{
    int i = blockIdx.x*256 + threadIdx.x;
    if (i < n) {
        int row = i / K, col = i % K;
        d[(size_t)row*K + PERM(col)] = tfr(s[i]);
    }
}

// ---------------- precompute: WU = blockdiag(Wq_h^T Wk_h) -------------------
// g_wu[640h+d, PERM(e)] = sum_i Wq[320h+i, e] * Wk[320h+i, d]
__global__ void wu_build(const float* __restrict__ ipw)
{
    __shared__ float wkc[8][320];
    int n0 = blockIdx.x * 8;            // grid 160; 640%8==0 -> single h/block
    int h = n0 / 640, d0 = n0 - h*640;
    for (int idx = threadIdx.x; idx < 8*320; idx += 128) {
        int r = idx / 320, i = idx % 320;
        wkc[r][i] = ipw[(size_t)(640 + 320*h + i)*640 + d0 + r];
    }
    __syncthreads();
    for (int t5 = 0; t5 < 5; t5++) {
        int e = threadIdx.x + t5*128;
        float acc[8] = {0,0,0,0,0,0,0,0};
        for (int i = 0; i < 320; i++) {
            float wq = ipw[(size_t)(320*h + i)*640 + e];
#pragma unroll
            for (int r = 0; r < 8; r++) acc[r] += wq * wkc[r][i];
        }
#pragma unroll
        for (int r = 0; r < 8; r++)
            g_wu[(size_t)(n0 + r)*640 + PERM(e)] = tfr(acc[r]);
    }
}

// cu[640h+d] = sum_i ipb[320h+i] * Wk[320h+i, d]   (q-bias folded into u1)
__global__ void cu_build(const float* __restrict__ ipw, const float* __restrict__ ipb)
{
    int n = blockIdx.x*128 + threadIdx.x;    // grid 10
    int h = n / 640, d = n - h*640;
    float a = 0.f;
    for (int i = 0; i < 320; i++)
        a += ipb[320*h + i] * ipw[(size_t)(640 + 320*h + i)*640 + d];
    g_cu[n] = a;
}

// Wq2 = outfn_w @ out_proj_w  ([128,640], fp32)
__global__ void w3_step1(const float* __restrict__ outfn_w, const float* __restrict__ opw)
{
    __shared__ float srow[4][640];
    int i0 = blockIdx.x * 4;    // grid 32
    for (int j = threadIdx.x; j < 4*640; j += 128)
        srow[j/640][j%640] = outfn_w[(size_t)(i0 + j/640)*640 + (j%640)];
    __syncthreads();
    for (int t = 0; t < 5; t++) {
        int d = threadIdx.x + t*128;
        float acc[4] = {0,0,0,0};
        for (int k = 0; k < 640; k++) {
            float w = opw[(size_t)k*640 + d];
#pragma unroll
            for (int r = 0; r < 4; r++) acc[r] += srow[r][k]*w;
        }
#pragma unroll
        for (int r = 0; r < 4; r++) g_wq2[(size_t)(i0+r)*640 + d] = acc[r];
    }
}
// W3[j,d] = sum_i Wq2[i,d] * attn_wq[i,j]   ([128,640], fp32, normal)
__global__ void w3_step2(const float* __restrict__ attn_wq)
{
    __shared__ float wqc[4][128];
    int j0 = blockIdx.x * 4;    // grid 32
    for (int idx = threadIdx.x; idx < 4*128; idx += 128) {
        int r = idx >> 7, i = idx & 127;
        wqc[r][i] = attn_wq[(size_t)i*128 + j0 + r];
    }
    __syncthreads();
    for (int t = 0; t < 5; t++) {
        int d = threadIdx.x + t*128;
        float acc[4] = {0,0,0,0};
        for (int i = 0; i < 128; i++) {
            float w = g_wq2[(size_t)i*640 + d];
#pragma unroll
            for (int r = 0; r < 4; r++) acc[r] += wqc[r][i]*w;
        }
#pragma unroll
        for (int r = 0; r < 4; r++) g_w3[(size_t)(j0+r)*640 + d] = acc[r];
    }
}
// bqh[j] = sum_i (outfn_b[i] + sum_k out_proj_b[k]*outfn_w[i,k]) * attn_wq[i,j]
__global__ void w3_bias(const float* __restrict__ opb, const float* __restrict__ outfn_w,
                        const float* __restrict__ outfn_b, const float* __restrict__ attn_wq)
{
    __shared__ float bq2[128];
    int i = threadIdx.x;
    float a = outfn_b[i];
    for (int k = 0; k < 640; k++) a += opb[k]*outfn_w[(size_t)i*640 + k];
    bq2[i] = a;
    __syncthreads();
    float s = 0.f;
    for (int ii = 0; ii < 128; ii++) s += bq2[ii]*attn_wq[(size_t)ii*128 + i];
    g_bqh[i] = s;
}

// W4[o, 640h+e] = sum_j W3[o, 320h+j] * Wv[320h+j, e]  (K-PERM, tf32)
__global__ void w4_build(const float* __restrict__ ipw)
{
    __shared__ float w3s[4][640];
    int o0 = blockIdx.x * 4;    // grid 32
    for (int idx = threadIdx.x; idx < 4*640; idx += 128)
        w3s[idx/640][idx%640] = g_w3[(size_t)(o0 + idx/640)*640 + (idx%640)];
    __syncthreads();
    for (int t10 = 0; t10 < 10; t10++) {
        int n = threadIdx.x + t10*128;   // 0..1279
        int h = n / 640, e = n - 640*h;
        float acc[4] = {0,0,0,0};
        for (int j = 0; j < 320; j++) {
            float wv = ipw[(size_t)(1280 + 320*h + j)*640 + e];
#pragma unroll
            for (int r = 0; r < 4; r++) acc[r] += w3s[r][320*h + j]*wv;
        }
        int np = PERM(n);
#pragma unroll
        for (int r = 0; r < 4; r++)
            g_w4[(size_t)(o0+r)*1280 + np] = tfr(acc[r]);
    }
}
// b4[o] = bqh[o] + sum_m W3[o,m] * ipb[1280+m]
__global__ void b4_build(const float* __restrict__ ipb)
{
    int o = threadIdx.x;
    float a = g_bqh[o];
    for (int m = 0; m < 640; m++) a += g_w3[(size_t)o*640 + m]*ipb[1280 + m];
    g_b4[o] = a;
}

// Wm2p[PERM(d)*128 + j] = sum_i attn_wv[d,i] * merge_w[i*128 + j]
__global__ void wm2_build(const float* __restrict__ awv, const float* __restrict__ mw)
{
    __shared__ float row[128];
    int d = blockIdx.x;                 // grid 384
    row[threadIdx.x] = awv[(size_t)d*128 + threadIdx.x];
    __syncthreads();
    int j = threadIdx.x;
    float a = 0.f;
    for (int i = 0; i < 128; i++) a += row[i]*mw[(size_t)i*128 + j];
    g_wm2p[(size_t)PERM(d)*128 + j] = a;
}

// ---------------- attention 1: scores via u1, output weighted sums s --------
__global__ void attn1_kernel(const int* __restrict__ hist_nids)
{
    int b = blockIdx.x, tid = threadIdx.x;   // 256 threads
    __shared__ float su[1280];
    __shared__ float sS[NHEAD*HL];
    __shared__ float sA[NHEAD*HL];
    for (int x = tid; x < 1280; x += 256)
        su[x] = g_u1[(size_t)b*1280 + PERM(x)];   // align to PERM-space full
    __syncthreads();

    int warp = tid >> 5, lane = tid & 31;
    for (int p = warp; p < NHEAD*HL; p += 8) {
        int h = p / HL, m = p % HL;
        const float* frow = g_full + (size_t)(b*HL + m)*DM;
        const float* urow = su + h*DM;
        float s = 0.f;
#pragma unroll
        for (int i = 0; i < 20; i++) { int d = lane + i*32; s += urow[d]*frow[d]; }
#pragma unroll
        for (int o = 16; o; o >>= 1) s += __shfl_xor_sync(0xffffffffu, s, o);
        if (!lane) sS[p] = s * 0.05590169943749474f;   // 1/sqrt(320)
    }
    __syncthreads();
    if (tid < NHEAD) {
        int h = tid;
        float sc[HL], mx = -1e30f;
        for (int m = 0; m < HL; m++) {
            float v = sS[h*HL + m];
            if (hist_nids[b*HL + m] == 0 && m != HL-1) v = -1e9f;
            sc[m] = v; mx = fmaxf(mx, v);
        }
        float sum = 0.f;
        for (int m = 0; m < HL; m++) { float e = expf(sc[m]-mx); sc[m] = e; sum += e; }
        float inv = 1.f/sum;
        for (int m = 0; m < HL; m++) sA[h*HL + m] = sc[m]*inv;
    }
    __syncthreads();
    for (int x = tid; x < 1280; x += 256) {
        int h = x / DM, e = x - h*DM;
        const float* fb = g_full + (size_t)b*HL*DM + e;
        float acc = 0.f;
#pragma unroll
        for (int m = 0; m < HL; m++) acc += sA[h*HL + m] * fb[(size_t)m*DM];
        g_s[(size_t)b*1280 + x] = tfr(acc);    // PERM space, feeds qh GEMM
    }
}

// ---------------- attention 2 + merge + GRU ---------------------------------
__global__ void attn2_gru_kernel(const int* __restrict__ nids,
                                 const int* __restrict__ hist_nids,
                                 const float* __restrict__ hist_ts,
                                 const float* __restrict__ node_feat,
                                 const float* __restrict__ merge_w,
                                 const float* __restrict__ merge_b,
                                 const float* __restrict__ gwhh,
                                 const float* __restrict__ gbhh,
                                 float* __restrict__ out)
{
    int b = blockIdx.x, tid = threadIdx.x;   // 128 threads
    __shared__ float su2[384], snf[128], ss2[384], sS[HL], sA[HL], shpl[NF];
#pragma unroll
    for (int q = 0; q < 3; q++) su2[tid + q*128] = g_u2[(size_t)b*384 + tid + q*128];
    snf[tid] = node_feat[(size_t)nids[b]*NF + tid];
    __syncthreads();
    int warp = tid >> 5, lane = tid & 31;
    for (int l = warp; l < HL; l += 4) {
        const float* nr = g_nb + (size_t)(b*HL + l)*384;
        float s = 0.f;
#pragma unroll
        for (int i = 0; i < 12; i++) { int d = lane + i*32; s += su2[d]*nr[d]; }
#pragma unroll
        for (int o = 16; o; o >>= 1) s += __shfl_xor_sync(0xffffffffu, s, o);
        if (!lane) sS[l] = s * 0.08838834764831845f;  // 1/sqrt(128)
    }
    __syncthreads();
    if (tid == 0) {
        float sc[HL], mx = -1e30f;
        for (int l = 0; l < HL; l++) {
            float v = sS[l];
            if (hist_nids[b*HL + l] == 0 && l != HL-1) v = -1e9f;
            sc[l] = v; mx = fmaxf(mx, v);
        }
        float sum = 0.f;
        for (int l = 0; l < HL; l++) { float e = expf(sc[l]-mx); sc[l] = e; sum += e; }
        float inv = 1.f/sum;
        for (int l = 0; l < HL; l++) sA[l] = sc[l]*inv;
    }
    __syncthreads();
#pragma unroll
    for (int q = 0; q < 3; q++) {
        int x = tid + q*128;
        const float* nbb = g_nb + (size_t)b*HL*384 + x;
        float acc = 0.f;
#pragma unroll
        for (int l = 0; l < HL; l++) acc += sA[l] * nbb[(size_t)l*384];
        ss2[x] = acc;
    }
    __syncthreads();

    // hpl = tanh(s2 @ Wm2 + nf @ merge_w[128:] + mb)
    float acc = merge_b[tid];
    for (int dp = 0; dp < 384; dp++)
        acc = fmaf(ss2[dp], g_wm2p[(size_t)dp*128 + tid], acc);
#pragma unroll 8
    for (int i = 0; i < 128; i++)
        acc = fmaf(snf[i], merge_w[(size_t)(128 + i)*128 + tid], acc);
    float hpl = tanhf(acc);
    shpl[tid] = hpl;
    __syncthreads();

    float gh[3];
#pragma unroll
    for (int c = 0; c < 3; c++) {
        int i = c*NF + tid;
        float a = gbhh[i];
        const float* wrow = gwhh + (size_t)i*NF;
#pragma unroll 8
        for (int k = 0; k < NF; k++) a = fmaf(shpl[k], wrow[k], a);
        gh[c] = a;
    }
    const float* gi = g_gi + (size_t)b*384;
    float r = 1.f/(1.f + expf(-(gi[tid]       + gh[0])));
    float z = 1.f/(1.f + expf(-(gi[NF + tid]  + gh[1])));
    float n = tanhf(gi[2*NF + tid] + r*gh[2]);
    float hpr = (1.f - z)*n + z*hpl;
    g_hpr[(size_t)b*NF + tid] = hpr;
    out[(size_t)BS*NF + (size_t)b*NF + tid] = hpr;        // h_right
    if (tid == 0) out[(size_t)2*BS*NF + b] = hist_ts[b*HL + HL-1];
}

// ---------------- ODE (RK4, 8 steps), 8 samples/block, weights in smem ------
__global__ __launch_bounds__(128)
void ode_kernel(const float* __restrict__ hist_ts,
                const float* __restrict__ tnw,
                const float* __restrict__ tnb,
                const float* __restrict__ odeb,
                float* __restrict__ out)
{
    extern __shared__ float sm[];           // wsm[16384] + ysm[128*8]
    float* wsm = sm;
    float* ysm = sm + NF*NF;
    int j = threadIdx.x;
    int b0 = blockIdx.x * 8;

    for (int i = j; i < NF*NF; i += 128) wsm[i] = g_odewT[i];
    float tw = tnw[j], tb = tnb[j], ob = odeb[j];
    float t0v[8], rat[8], z[8];
#pragma unroll
    for (int s = 0; s < 8; s++) {
        float a = hist_ts[(b0+s)*HL + HL-2];
        float b = hist_ts[(b0+s)*HL + HL-1];
        t0v[s] = a; rat[s] = b - a;
        z[s] = g_hpr[(size_t)(b0+s)*NF + j];
    }
    __syncthreads();
    const float ds = 1.f/ODE_STEPS;

    auto fstage = [&](float sfrac, const float* zi, float* f) {
        __syncthreads();
#pragma unroll
        for (int s = 0; s < 8; s++) {
            float te = __cosf((sfrac*rat[s] + t0v[s])*tw + tb);
            ysm[j*8 + s] = zi[s] + te;
        }
        __syncthreads();
        float acc[8];
#pragma unroll
        for (int s = 0; s < 8; s++) acc[s] = ob;
#pragma unroll 4
        for (int k = 0; k < NF; k++) {
            float w = wsm[k*NF + j];
            float4 y0 = *(const float4*)&ysm[k*8];
            float4 y1 = *(const float4*)&ysm[k*8 + 4];
            acc[0] = fmaf(y0.x, w, acc[0]);
            acc[1] = fmaf(y0.y, w, acc[1]);
            acc[2] = fmaf(y0.z, w, acc[2]);
            acc[3] = fmaf(y0.w, w, acc[3]);
            acc[4] = fmaf(y1.x, w, acc[4]);
            acc[5] = fmaf(y1.y, w, acc[5]);
            acc[6] = fmaf(y1.z, w, acc[6]);
            acc[7] = fmaf(y1.w, w, acc[7]);
        }
#pragma unroll
        for (int s = 0; s < 8; s++) {
            float th;
            asm("tanh.approx.f32 %0, %1;" : "=f"(th) : "f"(acc[s]));
            f[s] = th * rat[s];
        }
    };

    for (int i = 0; i < ODE_STEPS; i++) {
        float s0 = i * ds;
        float k1[8], k2[8], k3[8], k4[8], zi[8];
        fstage(s0, z, k1);
#pragma unroll
        for (int s = 0; s < 8; s++) zi[s] = z[s] + 0.5f*ds*k1[s];
        fstage(s0 + 0.5f*ds, zi, k2);
#pragma unroll
        for (int s = 0; s < 8; s++) zi[s] = z[s] + 0.5f*ds*k2[s];
        fstage(s0 + 0.5f*ds, zi, k3);
#pragma unroll
        for (int s = 0; s < 8; s++) zi[s] = z[s] + ds*k3[s];
        fstage(s0 + ds, zi, k4);
#pragma unroll
        for (int s = 0; s < 8; s++)
            z[s] += ds/6.f * (k1[s] + 2.f*k2[s] + 2.f*k3[s] + k4[s]);
    }
#pragma unroll
    for (int s = 0; s < 8; s++)
        out[(size_t)(b0+s)*NF + j] = z[s];   // h_left
}

// ---------------- host ------------------------------------------------------
extern "C" void kernel_launch(void* const* d_in, const int* in_sizes, int n_in,
                              void* d_out, int out_size)
{
    const int*   nids       = (const int*)  d_in[0];
    const int*   hist_nids  = (const int*)  d_in[2];
    const int*   aids       = (const int*)  d_in[3];
    const int*   eids       = (const int*)  d_in[4];
    const float* hist_ts    = (const float*)d_in[5];
    const int*   dirs       = (const int*)  d_in[6];
    const float* node_feat  = (const float*)d_in[7];
    const float* edge_feat  = (const float*)d_in[8];
    const float* anony_emb  = (const float*)d_in[9];
    const float* time_w     = (const float*)d_in[10];
    const float* time_b     = (const float*)d_in[11];
    const float* in_proj_w  = (const float*)d_in[12];
    const float* in_proj_b  = (const float*)d_in[13];
    const float* out_proj_w = (const float*)d_in[14];
    const float* out_proj_b = (const float*)d_in[15];
    const float* outfn_w    = (const float*)d_in[16];
    const float* outfn_b    = (const float*)d_in[17];
    const float* attn_wq    = (const float*)d_in[18];
    const float* attn_wk    = (const float*)d_in[19];
    const float* attn_wv    = (const float*)d_in[20];
    const float* merge_w    = (const float*)d_in[21];
    const float* merge_b    = (const float*)d_in[22];
    const float* gru_w_ih   = (const float*)d_in[23];
    const float* gru_w_hh   = (const float*)d_in[24];
    const float* gru_b_ih   = (const float*)d_in[25];
    const float* gru_b_hh   = (const float*)d_in[26];
    const float* ode_w      = (const float*)d_in[27];
    const float* ode_b      = (const float*)d_in[28];
    const float* tnode_w    = (const float*)d_in[29];
    const float* tnode_b    = (const float*)d_in[30];

    float* out = (float*)d_out;

    float *p_full, *p_lef, *p_u1, *p_s, *p_qh, *p_u2, *p_nb, *p_gi,
          *p_gwih, *p_wu, *p_cu, *p_w4, *p_b4, *p_wk2;
    cudaGetSymbolAddress((void**)&p_full,  g_full);
    cudaGetSymbolAddress((void**)&p_lef,   g_lef);
    cudaGetSymbolAddress((void**)&p_u1,    g_u1);
    cudaGetSymbolAddress((void**)&p_s,     g_s);
    cudaGetSymbolAddress((void**)&p_qh,    g_qh);
    cudaGetSymbolAddress((void**)&p_u2,    g_u2);
    cudaGetSymbolAddress((void**)&p_nb,    g_nb);
    cudaGetSymbolAddress((void**)&p_gi,    g_gi);
    cudaGetSymbolAddress((void**)&p_gwih,  g_gwih);
    cudaGetSymbolAddress((void**)&p_wu,    g_wu);
    cudaGetSymbolAddress((void**)&p_cu,    g_cu);
    cudaGetSymbolAddress((void**)&p_w4,    g_w4);
    cudaGetSymbolAddress((void**)&p_b4,    g_b4);
    cudaGetSymbolAddress((void**)&p_wk2,   g_wk2);

    cudaFuncSetAttribute(ode_kernel, cudaFuncAttributeMaxDynamicSharedMemorySize,
                         (NF*NF + NF*8) * 4);

    // --- gather + precompute (all small) ---
    build_kernel<<<BS*HL, 128>>>(nids, hist_nids, aids, eids, hist_ts, dirs,
                                 node_feat, edge_feat, anony_emb, time_w, time_b);
    transpose_odew<<<128, 128>>>(ode_w);
    cvt_tf32p<<<(384*512 + 255)/256, 256>>>(gru_w_ih, p_gwih, 512, 384*512);
    cvt_tf32p<<<(384*128 + 255)/256, 256>>>(attn_wk, p_wk2, 128, 384*128);
    wu_build<<<160, 128>>>(in_proj_w);
    cu_build<<<10, 128>>>(in_proj_w, in_proj_b);
    w3_step1<<<32, 128>>>(outfn_w, out_proj_w);
    w3_step2<<<32, 128>>>(attn_wq);
    w3_bias<<<1, 128>>>(out_proj_b, outfn_w, outfn_b, attn_wq);
    w4_build<<<32, 128>>>(in_proj_w);
    b4_build<<<1, 128>>>(in_proj_b);
    wm2_build<<<384, 128>>>(attn_wv, merge_w);

    // --- gi = lef @ gru_w_ih^T: [4096,512]x[384,512]^T ---
    tgemm<false><<<dim3(3, 32), 256>>>(DIN, p_lef, DIN, p_gwih, p_gi, 384, gru_b_ih);

    // --- u1 = full_last @ WU^T + cu: [4096,640]x[1280,640]^T ---
    tgemm<false><<<dim3(10, 32), 256>>>(DM, p_full + (size_t)(HL-1)*DM, HL*DM,
                                        p_wu, p_u1, 1280, p_cu);

    // --- attention 1: scores + weighted sums s ---
    attn1_kernel<<<BS, 256>>>(hist_nids);

    // --- qh = s @ W4^T + b4: [4096,1280]x[128,1280]^T (PERM out) ---
    tgemm<true><<<dim3(1, 32), 256>>>(1280, p_s, 1280, p_w4, p_qh, NF, p_b4);

    // --- u2 = qh @ attn_wk^T: [4096,128]x[384,128]^T (PERM out) ---
    tgemm<true><<<dim3(3, 32), 256>>>(NF, p_qh, NF, p_wk2, p_u2, 384,
                                      (const float*)nullptr);

    // --- attention 2 + merge + GRU (writes h_right + ts) ---
    attn2_gru_kernel<<<BS, 128>>>(nids, hist_nids, hist_ts, node_feat,
                                  merge_w, merge_b, gru_w_hh, gru_b_hh, out);

    // --- ODE RK4 (writes h_left) ---
    ode_kernel<<<BS/8, 128, (NF*NF + NF*8)*4>>>(hist_ts, tnode_w, tnode_b,
                                                ode_b, out);
}

// round 9
// speedup vs baseline: 1.4963x; 1.4295x over previous
#include <cuda_runtime.h>
#include <cuda_bf16.h>
#include <math.h>
#include <stdint.h>

// Problem constants
#define BS 4096
#define HL 20
#define NF 128
#define EF 128
#define TF 128
#define DM 640          // 3*NF + EF + TF
#define DIN 512         // DM - TF
#define NHEAD 2
#define DH 320          // DM / NHEAD
#define ODE_STEPS 8

// K-block interleave (4x4 transpose within each 16-block; self-inverse).
#define PERM(k) (((k) & ~15) | (((k) & 3) << 2) | (((k) & 15) >> 2))

// ---------------- scratch (device globals; no allocation allowed) ----------
__device__ float g_full [(size_t)BS*HL*DM];     // full_vals (tf32, PERM space)
__device__ float g_nb   [(size_t)BS*HL*384];    // nb (tf32, PERM space)
__device__ float g_lef  [(size_t)BS*DIN];       // last_event_feat (tf32, PERM)
__device__ float g_u1   [(size_t)BS*1280];      // u1 (normal cols)
__device__ float g_s    [(size_t)BS*1280];      // weighted sums (tf32, PERM)
__device__ float g_qh   [(size_t)BS*NF];        // qh (tf32, PERM via PERMOUT)
__device__ float g_u2   [(size_t)BS*384];       // u2 (tf32, PERM via PERMOUT)
__device__ float g_gi   [(size_t)BS*384];
__device__ float g_hpr  [(size_t)BS*NF];
__device__ float g_odewT[NF*NF];
__device__ float g_gwih [384*512];              // tf32+PERM gru_w_ih
__device__ float g_wu   [1280*640];             // WU (tf32, K-PERM)
__device__ float g_cu   [1280];                 // u1 bias
__device__ float g_wq2  [128*640];              // outfn_w @ out_proj_w (fp32)
__device__ float g_w3   [128*640];              // attn_wq^T outfn out_proj (fp32)
__device__ float g_bq2  [128];
__device__ float g_w4   [128*1280];             // W3 folded with Wv (tf32, K-PERM)
__device__ float g_b4   [128];
__device__ float g_wk2  [384*128];              // attn_wk (tf32, K-PERM)
__device__ float g_wm2p [384*128];              // attn_wv @ merge_w_top, rows PERM

__device__ __forceinline__ uint32_t f2tf(float x) {
    uint32_t u; asm("cvt.rna.tf32.f32 %0, %1;" : "=r"(u) : "f"(x)); return u;
}
__device__ __forceinline__ float tfr(float x) { return __uint_as_float(f2tf(x)); }

__device__ __forceinline__ void cp16(uint32_t dst, const void* src) {
    asm volatile("cp.async.cg.shared.global [%0], [%1], 16;" :: "r"(dst), "l"(src));
}

// ---------------- TF32 mma.sync GEMM, TN form, K-interleaved operands -------
template<bool PERMOUT>
__global__ __launch_bounds__(256, 2)
void tgemm(int K, const float* __restrict__ A, int lda,
           const float* __restrict__ B,
           float* __restrict__ C, int ldc,
           const float* __restrict__ bias)
{
    __shared__ float As[3][128][16];
    __shared__ float Bs[3][128][16];
    int tid = threadIdx.x;
    int warp = tid >> 5, lane = tid & 31;
    int row0 = blockIdx.y * 128, col0 = blockIdx.x * 128;
    int m0 = (warp >> 1) * 32, n0 = (warp & 1) * 64;
    int g = lane >> 2, t = lane & 3;

    float c[2][8][4];
#pragma unroll
    for (int mi = 0; mi < 2; mi++)
#pragma unroll
        for (int ni = 0; ni < 8; ni++)
#pragma unroll
            for (int i = 0; i < 4; i++) c[mi][ni][i] = 0.f;

    const float* Ap = A + (size_t)row0 * lda;
    const float* Bp = B + (size_t)col0 * K;

    uint32_t sA = (uint32_t)__cvta_generic_to_shared(&As[0][0][0]);
    uint32_t sB = (uint32_t)__cvta_generic_to_shared(&Bs[0][0][0]);
    const uint32_t stg = 128u*16u*4u;

#define LOADSTAGE(s, kt) {                                                    \
        _Pragma("unroll")                                                     \
        for (int i = 0; i < 2; i++) {                                         \
            int j = tid + i*256, r = j >> 2, q = j & 3;                       \
            cp16(sA + (uint32_t)(s)*stg + (uint32_t)(r*16 + q*4)*4u,          \
                 Ap + (size_t)r*lda + (kt)*16 + q*4);                         \
            cp16(sB + (uint32_t)(s)*stg + (uint32_t)(r*16 + q*4)*4u,          \
                 Bp + (size_t)r*K + (kt)*16 + q*4);                           \
        }                                                                     \
        asm volatile("cp.async.commit_group;" ::: "memory");                  \
    }

    int T = K >> 4;
    LOADSTAGE(0, 0);
    LOADSTAGE(1, 1);

    int s = 0, sw = 2;
    for (int kt = 0; kt < T; kt++) {
        if (kt + 1 < T) asm volatile("cp.async.wait_group 1;" ::: "memory");
        else            asm volatile("cp.async.wait_group 0;" ::: "memory");
        __syncthreads();
        if (kt + 2 < T) LOADSTAGE(sw, kt + 2);

        float4 av[2][2], bv[8];
#pragma unroll
        for (int mi = 0; mi < 2; mi++) {
            int rm = m0 + mi*16 + g;
            av[mi][0] = *(const float4*)&As[s][rm    ][t*4];
            av[mi][1] = *(const float4*)&As[s][rm + 8][t*4];
        }
#pragma unroll
        for (int ni = 0; ni < 8; ni++) {
            int cn = n0 + ni*8 + g;
            bv[ni] = *(const float4*)&Bs[s][cn][t*4];
        }
#pragma unroll
        for (int mi = 0; mi < 2; mi++)
#pragma unroll
            for (int ni = 0; ni < 8; ni++) {
                asm volatile(
                    "mma.sync.aligned.m16n8k8.row.col.f32.tf32.tf32.f32 "
                    "{%0,%1,%2,%3},{%4,%5,%6,%7},{%8,%9},{%0,%1,%2,%3};\n"
                    : "+f"(c[mi][ni][0]), "+f"(c[mi][ni][1]),
                      "+f"(c[mi][ni][2]), "+f"(c[mi][ni][3])
                    : "r"(__float_as_uint(av[mi][0].x)), "r"(__float_as_uint(av[mi][1].x)),
                      "r"(__float_as_uint(av[mi][0].y)), "r"(__float_as_uint(av[mi][1].y)),
                      "r"(__float_as_uint(bv[ni].x)),    "r"(__float_as_uint(bv[ni].y)));
                asm volatile(
                    "mma.sync.aligned.m16n8k8.row.col.f32.tf32.tf32.f32 "
                    "{%0,%1,%2,%3},{%4,%5,%6,%7},{%8,%9},{%0,%1,%2,%3};\n"
                    : "+f"(c[mi][ni][0]), "+f"(c[mi][ni][1]),
                      "+f"(c[mi][ni][2]), "+f"(c[mi][ni][3])
                    : "r"(__float_as_uint(av[mi][0].z)), "r"(__float_as_uint(av[mi][1].z)),
                      "r"(__float_as_uint(av[mi][0].w)), "r"(__float_as_uint(av[mi][1].w)),
                      "r"(__float_as_uint(bv[ni].z)),    "r"(__float_as_uint(bv[ni].w)));
            }
        __syncthreads();
        s  = (s  == 2) ? 0 : s  + 1;
        sw = (sw == 2) ? 0 : sw + 1;
    }

#pragma unroll
    for (int mi = 0; mi < 2; mi++) {
        size_t r1 = (size_t)(row0 + m0 + mi*16 + g);
        size_t r2 = r1 + 8;
#pragma unroll
        for (int ni = 0; ni < 8; ni++) {
            int cc = col0 + n0 + ni*8 + 2*t;
            float b0 = 0.f, b1 = 0.f;
            if (bias) { b0 = bias[cc]; b1 = bias[cc + 1]; }
            float v0 = c[mi][ni][0] + b0, v1 = c[mi][ni][1] + b1;
            float v2 = c[mi][ni][2] + b0, v3 = c[mi][ni][3] + b1;
            if (PERMOUT) {
                int p0 = PERM(cc), p1 = PERM(cc + 1);
                C[r1*ldc + p0] = tfr(v0); C[r1*ldc + p1] = tfr(v1);
                C[r2*ldc + p0] = tfr(v2); C[r2*ldc + p1] = tfr(v3);
            } else {
                *(float2*)&C[r1*ldc + cc] = make_float2(v0, v1);
                *(float2*)&C[r2*ldc + cc] = make_float2(v2, v3);
            }
        }
    }
#undef LOADSTAGE
}

// ---------------- generic small SIMT GEMM (precompute path) ------------------
// TRANSA=1: C[m,n] = sum_k A[k*lda + m] * B[k*ldb + n]   (outer-TN)
// TRANSA=0: C[m,n] = sum_k A[m*lda + k] * B[k*ldb + n]   (NN)
// TFPERM: C col index PERM'd + tf32-rounded. PERMROW: C row index PERM'd.
// M%64==0, N%64==0, K%16==0. grid=(N/64, M/64), 256 threads.
template<bool TRANSA, bool TFPERM, bool PERMROW>
__global__ __launch_bounds__(256)
void sgemm_small(int M, int N, int K,
                 const float* __restrict__ A, int lda,
                 const float* __restrict__ B, int ldb,
                 float* __restrict__ C, int ldc)
{
    __shared__ float As[16][64];
    __shared__ float Bs[16][64];
    int tid = threadIdx.x;
    int m0 = blockIdx.y*64, n0 = blockIdx.x*64;
    int tx = tid & 15, ty = tid >> 4;
    float acc[4][4];
#pragma unroll
    for (int i = 0; i < 4; i++)
#pragma unroll
        for (int j = 0; j < 4; j++) acc[i][j] = 0.f;

    for (int k0 = 0; k0 < K; k0 += 16) {
        if (TRANSA) {
            for (int i = tid; i < 1024; i += 256) {
                int kk = i >> 6, mm = i & 63;
                As[kk][mm] = A[(size_t)(k0+kk)*lda + m0 + mm];
            }
        } else {
            for (int i = tid; i < 1024; i += 256) {
                int mm = i >> 4, kk = i & 15;
                As[kk][mm] = A[(size_t)(m0+mm)*lda + k0 + kk];
            }
        }
        for (int i = tid; i < 1024; i += 256) {
            int kk = i >> 6, nn = i & 63;
            Bs[kk][nn] = B[(size_t)(k0+kk)*ldb + n0 + nn];
        }
        __syncthreads();
#pragma unroll
        for (int kk = 0; kk < 16; kk++) {
            float4 a4 = *(const float4*)&As[kk][ty*4];
            float4 b4 = *(const float4*)&Bs[kk][tx*4];
            float a[4] = {a4.x, a4.y, a4.z, a4.w};
            float b[4] = {b4.x, b4.y, b4.z, b4.w};
#pragma unroll
            for (int i = 0; i < 4; i++)
#pragma unroll
                for (int j = 0; j < 4; j++)
                    acc[i][j] = fmaf(a[i], b[j], acc[i][j]);
        }
        __syncthreads();
    }
#pragma unroll
    for (int i = 0; i < 4; i++) {
        int m = m0 + ty*4 + i;
        size_t row = PERMROW ? (size_t)PERM(m) : (size_t)m;
#pragma unroll
        for (int j = 0; j < 4; j++) {
            int n = n0 + tx*4 + j;
            if (TFPERM) C[row*ldc + PERM(n)] = tfr(acc[i][j]);
            else        C[row*ldc + n]       = acc[i][j];
        }
    }
}

// ---------------- build full_vals, nb, last_event_feat (tf32 + PERM) -------
__global__ void build_kernel(const int* __restrict__ nids,
                             const int* __restrict__ hist_nids,
                             const int* __restrict__ aids,
                             const int* __restrict__ eids,
                             const float* __restrict__ hist_ts,
                             const int* __restrict__ dirs,
                             const float* __restrict__ node_feat,
                             const float* __restrict__ edge_feat,
                             const float* __restrict__ anony,
                             const float* __restrict__ tw,
                             const float* __restrict__ tb)
{
    int bl = blockIdx.x;            // b*HL + l
    int b  = bl / HL, l = bl % HL;
    int j  = threadIdx.x;           // 0..127
    int jp = PERM(j);
    int hn  = hist_nids[bl];
    int dir = dirs[bl];
    int nid = nids[b];
    int src = dir ? nid : hn;
    int dst = dir ? hn  : nid;
    float sv = tfr(node_feat[(size_t)src*NF + j]);
    float dv = tfr(node_feat[(size_t)dst*NF + j]);
    float av = tfr(anony[(size_t)aids[bl]*NF + j]);
    float ev = tfr(edge_feat[(size_t)eids[bl]*EF + j]);
    float dt = hist_ts[b*HL + HL-1] - hist_ts[bl];
    float tv = tfr(cosf(dt*tw[j] + tb[j]));

    float* fv = g_full + (size_t)bl*DM;
    if (l == HL-1) {
        float* lef = g_lef + (size_t)b*DIN;
        lef[jp] = sv; lef[NF+jp] = dv; lef[2*NF+jp] = av; lef[3*NF+jp] = ev;
        fv[jp] = 0.f; fv[NF+jp] = 0.f; fv[2*NF+jp] = 0.f; fv[3*NF+jp] = 0.f;
        fv[4*NF+jp] = tv;
    } else {
        fv[jp] = sv; fv[NF+jp] = dv; fv[2*NF+jp] = av; fv[3*NF+jp] = ev;
        fv[4*NF+jp] = tv;
    }
    float* nb = g_nb + (size_t)bl*384;
    nb[jp]        = tfr(node_feat[(size_t)hn*NF + j]);
    nb[NF + jp]   = ev;
    nb[2*NF + jp] = tv;
}

__global__ void transpose_odew(const float* __restrict__ w)
{
    int idx = blockIdx.x*128 + threadIdx.x;
    int j = idx >> 7, k = idx & 127;
    g_odewT[k*NF + j] = w[idx];
}

// tf32-round + K-permute columns of a row-major [rows, K] matrix
__global__ void cvt_tf32p(const float* __restrict__ s, float* __restrict__ d,
                          int K, int n)
{
    int i = blockIdx.x*256 + threadIdx.x;
    if (i < n) {
        int row = i / K, col = i % K;
        d[(size_t)row*K + PERM(col)] = tfr(s[i]);
    }
}

// ---------------- bias precomputes (block-per-output reductions) ------------
__device__ __forceinline__ float block_reduce(float s)
{
    __shared__ float red[4];
    for (int o = 16; o; o >>= 1) s += __shfl_xor_sync(0xffffffffu, s, o);
    if ((threadIdx.x & 31) == 0) red[threadIdx.x >> 5] = s;
    __syncthreads();
    return red[0] + red[1] + red[2] + red[3];
}

// cu[640h+d] = sum_i ipb[320h+i] * Wk[320h+i, d]
__global__ void cu_build(const float* __restrict__ ipw, const float* __restrict__ ipb)
{
    int n = blockIdx.x;                 // grid 1280
    int h = n / 640, d = n - h*640;
    float s = 0.f;
    for (int i = threadIdx.x; i < 320; i += 128)
        s += ipb[320*h + i] * ipw[(size_t)(640 + 320*h + i)*640 + d];
    float tot = block_reduce(s);
    if (threadIdx.x == 0) g_cu[n] = tot;
}

// bq2[i] = outfn_b[i] + sum_k out_proj_b[k]*outfn_w[i,k]
__global__ void bq2_build(const float* __restrict__ opb,
                          const float* __restrict__ outfn_w,
                          const float* __restrict__ outfn_b)
{
    int i = blockIdx.x;                 // grid 128
    float s = 0.f;
    for (int k = threadIdx.x; k < 640; k += 128)
        s += opb[k] * outfn_w[(size_t)i*640 + k];
    float tot = block_reduce(s);
    if (threadIdx.x == 0) g_bq2[i] = outfn_b[i] + tot;
}

// b4[o] = sum_i bq2[i]*awq[i,o] + sum_m W3[o,m]*ipb[1280+m]
__global__ void b4_build(const float* __restrict__ awq, const float* __restrict__ ipb)
{
    int o = blockIdx.x;                 // grid 128
    int t = threadIdx.x;
    float s = g_bq2[t] * awq[(size_t)t*128 + o];
    for (int m = t; m < 640; m += 128)
        s += g_w3[(size_t)o*640 + m] * ipb[1280 + m];
    float tot = block_reduce(s);
    if (threadIdx.x == 0) g_b4[o] = tot;
}

// ---------------- attention 1: scores via u1, output weighted sums s --------
__global__ void attn1_kernel(const int* __restrict__ hist_nids)
{
    int b = blockIdx.x, tid = threadIdx.x;   // 256 threads
    __shared__ float su[1280];
    __shared__ float sS[NHEAD*HL];
    __shared__ float sA[NHEAD*HL];
    for (int x = tid; x < 1280; x += 256)
        su[x] = g_u1[(size_t)b*1280 + PERM(x)];   // align to PERM-space full
    __syncthreads();

    int warp = tid >> 5, lane = tid & 31;
    for (int p = warp; p < NHEAD*HL; p += 8) {
        int h = p / HL, m = p % HL;
        const float* frow = g_full + (size_t)(b*HL + m)*DM;
        const float* urow = su + h*DM;
        float s = 0.f;
#pragma unroll
        for (int i = 0; i < 20; i++) { int d = lane + i*32; s += urow[d]*frow[d]; }
#pragma unroll
        for (int o = 16; o; o >>= 1) s += __shfl_xor_sync(0xffffffffu, s, o);
        if (!lane) sS[p] = s * 0.05590169943749474f;   // 1/sqrt(320)
    }
    __syncthreads();
    if (tid < NHEAD) {
        int h = tid;
        float sc[HL], mx = -1e30f;
        for (int m = 0; m < HL; m++) {
            float v = sS[h*HL + m];
            if (hist_nids[b*HL + m] == 0 && m != HL-1) v = -1e9f;
            sc[m] = v; mx = fmaxf(mx, v);
        }
        float sum = 0.f;
        for (int m = 0; m < HL; m++) { float e = expf(sc[m]-mx); sc[m] = e; sum += e; }
        float inv = 1.f/sum;
        for (int m = 0; m < HL; m++) sA[h*HL + m] = sc[m]*inv;
    }
    __syncthreads();
    for (int x = tid; x < 1280; x += 256) {
        int h = x / DM, e = x - h*DM;
        const float* fb = g_full + (size_t)b*HL*DM + e;
        float acc = 0.f;
#pragma unroll
        for (int m = 0; m < HL; m++) acc += sA[h*HL + m] * fb[(size_t)m*DM];
        g_s[(size_t)b*1280 + x] = tfr(acc);    // PERM space, feeds qh GEMM
    }
}

// ---------------- attention 2 + merge + GRU ---------------------------------
__global__ void attn2_gru_kernel(const int* __restrict__ nids,
                                 const int* __restrict__ hist_nids,
                                 const float* __restrict__ hist_ts,
                                 const float* __restrict__ node_feat,
                                 const float* __restrict__ merge_w,
                                 const float* __restrict__ merge_b,
                                 const float* __restrict__ gwhh,
                                 const float* __restrict__ gbhh,
                                 float* __restrict__ out)
{
    int b = blockIdx.x, tid = threadIdx.x;   // 128 threads
    __shared__ float su2[384], snf[128], ss2[384], sS[HL], sA[HL], shpl[NF];
#pragma unroll
    for (int q = 0; q < 3; q++) su2[tid + q*128] = g_u2[(size_t)b*384 + tid + q*128];
    snf[tid] = node_feat[(size_t)nids[b]*NF + tid];
    __syncthreads();
    int warp = tid >> 5, lane = tid & 31;
    for (int l = warp; l < HL; l += 4) {
        const float* nr = g_nb + (size_t)(b*HL + l)*384;
        float s = 0.f;
#pragma unroll
        for (int i = 0; i < 12; i++) { int d = lane + i*32; s += su2[d]*nr[d]; }
#pragma unroll
        for (int o = 16; o; o >>= 1) s += __shfl_xor_sync(0xffffffffu, s, o);
        if (!lane) sS[l] = s * 0.08838834764831845f;  // 1/sqrt(128)
    }
    __syncthreads();
    if (tid == 0) {
        float sc[HL], mx = -1e30f;
        for (int l = 0; l < HL; l++) {
            float v = sS[l];
            if (hist_nids[b*HL + l] == 0 && l != HL-1) v = -1e9f;
            sc[l] = v; mx = fmaxf(mx, v);
        }
        float sum = 0.f;
        for (int l = 0; l < HL; l++) { float e = expf(sc[l]-mx); sc[l] = e; sum += e; }
        float inv = 1.f/sum;
        for (int l = 0; l < HL; l++) sA[l] = sc[l]*inv;
    }
    __syncthreads();
#pragma unroll
    for (int q = 0; q < 3; q++) {
        int x = tid + q*128;
        const float* nbb = g_nb + (size_t)b*HL*384 + x;
        float acc = 0.f;
#pragma unroll
        for (int l = 0; l < HL; l++) acc += sA[l] * nbb[(size_t)l*384];
        ss2[x] = acc;
    }
    __syncthreads();

    // hpl = tanh(s2 @ Wm2 + nf @ merge_w[128:] + mb)
    float acc = merge_b[tid];
    for (int dp = 0; dp < 384; dp++)
        acc = fmaf(ss2[dp], g_wm2p[(size_t)dp*128 + tid], acc);
#pragma unroll 8
    for (int i = 0; i < 128; i++)
        acc = fmaf(snf[i], merge_w[(size_t)(128 + i)*128 + tid], acc);
    float hpl = tanhf(acc);
    shpl[tid] = hpl;
    __syncthreads();

    float gh[3];
#pragma unroll
    for (int c = 0; c < 3; c++) {
        int i = c*NF + tid;
        float a = gbhh[i];
        const float* wrow = gwhh + (size_t)i*NF;
#pragma unroll 8
        for (int k = 0; k < NF; k++) a = fmaf(shpl[k], wrow[k], a);
        gh[c] = a;
    }
    const float* gi = g_gi + (size_t)b*384;
    float r = 1.f/(1.f + expf(-(gi[tid]       + gh[0])));
    float z = 1.f/(1.f + expf(-(gi[NF + tid]  + gh[1])));
    float n = tanhf(gi[2*NF + tid] + r*gh[2]);
    float hpr = (1.f - z)*n + z*hpl;
    g_hpr[(size_t)b*NF + tid] = hpr;
    out[(size_t)BS*NF + (size_t)b*NF + tid] = hpr;        // h_right
    if (tid == 0) out[(size_t)2*BS*NF + b] = hist_ts[b*HL + HL-1];
}

// ---------------- ODE (RK4, 8 steps), 8 samples/block, weights in smem ------
__global__ __launch_bounds__(128)
void ode_kernel(const float* __restrict__ hist_ts,
                const float* __restrict__ tnw,
                const float* __restrict__ tnb,
                const float* __restrict__ odeb,
                float* __restrict__ out)
{
    extern __shared__ float sm[];           // wsm[16384] + ysm[128*8]
    float* wsm = sm;
    float* ysm = sm + NF*NF;
    int j = threadIdx.x;
    int b0 = blockIdx.x * 8;

    for (int i = j; i < NF*NF; i += 128) wsm[i] = g_odewT[i];
    float tw = tnw[j], tb = tnb[j], ob = odeb[j];
    float t0v[8], rat[8], z[8];
#pragma unroll
    for (int s = 0; s < 8; s++) {
        float a = hist_ts[(b0+s)*HL + HL-2];
        float b = hist_ts[(b0+s)*HL + HL-1];
        t0v[s] = a; rat[s] = b - a;
        z[s] = g_hpr[(size_t)(b0+s)*NF + j];
    }
    __syncthreads();
    const float ds = 1.f/ODE_STEPS;

    auto fstage = [&](float sfrac, const float* zi, float* f) {
        __syncthreads();
#pragma unroll
        for (int s = 0; s < 8; s++) {
            float te = __cosf((sfrac*rat[s] + t0v[s])*tw + tb);
            ysm[j*8 + s] = zi[s] + te;
        }
        __syncthreads();
        float acc[8];
#pragma unroll
        for (int s = 0; s < 8; s++) acc[s] = ob;
#pragma unroll 4
        for (int k = 0; k < NF; k++) {
            float w = wsm[k*NF + j];
            float4 y0 = *(const float4*)&ysm[k*8];
            float4 y1 = *(const float4*)&ysm[k*8 + 4];
            acc[0] = fmaf(y0.x, w, acc[0]);
            acc[1] = fmaf(y0.y, w, acc[1]);
            acc[2] = fmaf(y0.z, w, acc[2]);
            acc[3] = fmaf(y0.w, w, acc[3]);
            acc[4] = fmaf(y1.x, w, acc[4]);
            acc[5] = fmaf(y1.y, w, acc[5]);
            acc[6] = fmaf(y1.z, w, acc[6]);
            acc[7] = fmaf(y1.w, w, acc[7]);
        }
#pragma unroll
        for (int s = 0; s < 8; s++) {
            float th;
            asm("tanh.approx.f32 %0, %1;" : "=f"(th) : "f"(acc[s]));
            f[s] = th * rat[s];
        }
    };

    for (int i = 0; i < ODE_STEPS; i++) {
        float s0 = i * ds;
        float k1[8], k2[8], k3[8], k4[8], zi[8];
        fstage(s0, z, k1);
#pragma unroll
        for (int s = 0; s < 8; s++) zi[s] = z[s] + 0.5f*ds*k1[s];
        fstage(s0 + 0.5f*ds, zi, k2);
#pragma unroll
        for (int s = 0; s < 8; s++) zi[s] = z[s] + 0.5f*ds*k2[s];
        fstage(s0 + 0.5f*ds, zi, k3);
#pragma unroll
        for (int s = 0; s < 8; s++) zi[s] = z[s] + ds*k3[s];
        fstage(s0 + ds, zi, k4);
#pragma unroll
        for (int s = 0; s < 8; s++)
            z[s] += ds/6.f * (k1[s] + 2.f*k2[s] + 2.f*k3[s] + k4[s]);
    }
#pragma unroll
    for (int s = 0; s < 8; s++)
        out[(size_t)(b0+s)*NF + j] = z[s];   // h_left
}

// ---------------- host ------------------------------------------------------
extern "C" void kernel_launch(void* const* d_in, const int* in_sizes, int n_in,
                              void* d_out, int out_size)
{
    const int*   nids       = (const int*)  d_in[0];
    const int*   hist_nids  = (const int*)  d_in[2];
    const int*   aids       = (const int*)  d_in[3];
    const int*   eids       = (const int*)  d_in[4];
    const float* hist_ts    = (const float*)d_in[5];
    const int*   dirs       = (const int*)  d_in[6];
    const float* node_feat  = (const float*)d_in[7];
    const float* edge_feat  = (const float*)d_in[8];
    const float* anony_emb  = (const float*)d_in[9];
    const float* time_w     = (const float*)d_in[10];
    const float* time_b     = (const float*)d_in[11];
    const float* in_proj_w  = (const float*)d_in[12];
    const float* in_proj_b  = (const float*)d_in[13];
    const float* out_proj_w = (const float*)d_in[14];
    const float* out_proj_b = (const float*)d_in[15];
    const float* outfn_w    = (const float*)d_in[16];
    const float* outfn_b    = (const float*)d_in[17];
    const float* attn_wq    = (const float*)d_in[18];
    const float* attn_wk    = (const float*)d_in[19];
    const float* attn_wv    = (const float*)d_in[20];
    const float* merge_w    = (const float*)d_in[21];
    const float* merge_b    = (const float*)d_in[22];
    const float* gru_w_ih   = (const float*)d_in[23];
    const float* gru_w_hh   = (const float*)d_in[24];
    const float* gru_b_ih   = (const float*)d_in[25];
    const float* gru_b_hh   = (const float*)d_in[26];
    const float* ode_w      = (const float*)d_in[27];
    const float* ode_b      = (const float*)d_in[28];
    const float* tnode_w    = (const float*)d_in[29];
    const float* tnode_b    = (const float*)d_in[30];

    float* out = (float*)d_out;

    float *p_full, *p_lef, *p_u1, *p_s, *p_qh, *p_u2, *p_gi,
          *p_gwih, *p_wu, *p_cu, *p_wq2, *p_w3, *p_w4, *p_b4, *p_wk2, *p_wm2p;
    cudaGetSymbolAddress((void**)&p_full,  g_full);
    cudaGetSymbolAddress((void**)&p_lef,   g_lef);
    cudaGetSymbolAddress((void**)&p_u1,    g_u1);
    cudaGetSymbolAddress((void**)&p_s,     g_s);
    cudaGetSymbolAddress((void**)&p_qh,    g_qh);
    cudaGetSymbolAddress((void**)&p_u2,    g_u2);
    cudaGetSymbolAddress((void**)&p_gi,    g_gi);
    cudaGetSymbolAddress((void**)&p_gwih,  g_gwih);
    cudaGetSymbolAddress((void**)&p_wu,    g_wu);
    cudaGetSymbolAddress((void**)&p_cu,    g_cu);
    cudaGetSymbolAddress((void**)&p_wq2,   g_wq2);
    cudaGetSymbolAddress((void**)&p_w3,    g_w3);
    cudaGetSymbolAddress((void**)&p_w4,    g_w4);
    cudaGetSymbolAddress((void**)&p_b4,    g_b4);
    cudaGetSymbolAddress((void**)&p_wk2,   g_wk2);
    cudaGetSymbolAddress((void**)&p_wm2p,  g_wm2p);

    cudaFuncSetAttribute(ode_kernel, cudaFuncAttributeMaxDynamicSharedMemorySize,
                         (NF*NF + NF*8) * 4);

    // --- gather (big, parallel) ---
    build_kernel<<<BS*HL, 128>>>(nids, hist_nids, aids, eids, hist_ts, dirs,
                                 node_feat, edge_feat, anony_emb, time_w, time_b);

    // --- precompute: all wide-parallel now ---
    transpose_odew<<<128, 128>>>(ode_w);
    cvt_tf32p<<<(384*512 + 255)/256, 256>>>(gru_w_ih, p_gwih, 512, 384*512);
    cvt_tf32p<<<(384*128 + 255)/256, 256>>>(attn_wk, p_wk2, 128, 384*128);

    // WU_h = Wk_h(outer) x Wq_h: C[d,e], tf32+PERM cols
    for (int h = 0; h < 2; h++)
        sgemm_small<true, true, false><<<dim3(10, 10), 256>>>(
            640, 640, 320,
            in_proj_w + (size_t)(640 + 320*h)*640, 640,
            in_proj_w + (size_t)(320*h)*640, 640,
            p_wu + (size_t)(640*h)*640, 640);
    cu_build<<<1280, 128>>>(in_proj_w, in_proj_b);

    // Wq2 = outfn_w @ out_proj_w (NN)
    sgemm_small<false, false, false><<<dim3(10, 2), 256>>>(
        128, 640, 640, outfn_w, 640, out_proj_w, 640, p_wq2, 640);
    // W3 = awq^T @ Wq2 (outer-TN)
    sgemm_small<true, false, false><<<dim3(10, 2), 256>>>(
        128, 640, 128, attn_wq, 128, p_wq2, 640, p_w3, 640);
    // W4_h = W3[:,320h:] @ Wv_h (NN), tf32+PERM cols
    for (int h = 0; h < 2; h++)
        sgemm_small<false, true, false><<<dim3(10, 2), 256>>>(
            128, 640, 320,
            p_w3 + 320*h, 640,
            in_proj_w + (size_t)(1280 + 320*h)*640, 640,
            p_w4 + 640*h, 1280);
    bq2_build<<<128, 128>>>(out_proj_b, outfn_w, outfn_b);
    b4_build<<<128, 128>>>(attn_wq, in_proj_b);

    // wm2p = awv @ merge_w_top (NN), PERM rows
    sgemm_small<false, false, true><<<dim3(2, 6), 256>>>(
        384, 128, 128, attn_wv, 128, merge_w, 128, p_wm2p, 128);

    // --- gi = lef @ gru_w_ih^T: [4096,512]x[384,512]^T ---
    tgemm<false><<<dim3(3, 32), 256>>>(DIN, p_lef, DIN, p_gwih, p_gi, 384, gru_b_ih);

    // --- u1 = full_last @ WU^T + cu: [4096,640]x[1280,640]^T ---
    tgemm<false><<<dim3(10, 32), 256>>>(DM, p_full + (size_t)(HL-1)*DM, HL*DM,
                                        p_wu, p_u1, 1280, p_cu);

    // --- attention 1: scores + weighted sums s ---
    attn1_kernel<<<BS, 256>>>(hist_nids);

    // --- qh = s @ W4^T + b4: [4096,1280]x[128,1280]^T (PERM out) ---
    tgemm<true><<<dim3(1, 32), 256>>>(1280, p_s, 1280, p_w4, p_qh, NF, p_b4);

    // --- u2 = qh @ attn_wk^T: [4096,128]x[384,128]^T (PERM out) ---
    tgemm<true><<<dim3(3, 32), 256>>>(NF, p_qh, NF, p_wk2, p_u2, 384,
                                      (const float*)nullptr);

    // --- attention 2 + merge + GRU (writes h_right + ts) ---
    attn2_gru_kernel<<<BS, 128>>>(nids, hist_nids, hist_ts, node_feat,
                                  merge_w, merge_b, gru_w_hh, gru_b_hh, out);

    // --- ODE RK4 (writes h_left) ---
    ode_kernel<<<BS/8, 128, (NF*NF + NF*8)*4>>>(hist_ts, tnode_w, tnode_b,
                                                ode_b, out);
}

// round 11
// speedup vs baseline: 2.2830x; 1.5258x over previous
#include <cuda_runtime.h>
#include <cuda_bf16.h>
#include <math.h>
#include <stdint.h>

// Problem constants
#define BS 4096
#define HL 20
#define NF 128
#define EF 128
#define TF 128
#define DM 640          // 3*NF + EF + TF
#define DIN 512         // DM - TF
#define NHEAD 2
#define DH 320          // DM / NHEAD
#define ODE_STEPS 8

// K-block interleave (4x4 transpose within each 16-block; self-inverse).
#define PERM(k) (((k) & ~15) | (((k) & 3) << 2) | (((k) & 15) >> 2))

// ---------------- scratch (device globals; no allocation allowed) ----------
__device__ float g_full [(size_t)BS*HL*DM];     // full_vals (tf32, PERM space)
__device__ float g_nb   [(size_t)BS*HL*384];    // nb (tf32, PERM space)
__device__ float g_lef  [(size_t)BS*DIN];       // last_event_feat (tf32, PERM)
__device__ float g_u1   [(size_t)BS*1280];      // u1 (normal cols)
__device__ float g_s    [(size_t)BS*1280];      // weighted sums (tf32, PERM)
__device__ float g_qh   [(size_t)BS*NF];        // qh (tf32, PERM)
__device__ float g_u2   [(size_t)BS*384];       // u2 (tf32, PERM)
__device__ float g_gi   [(size_t)BS*384];
__device__ float g_cat2 [(size_t)BS*512];       // [ss2|nf] (tf32, PERM)
__device__ float g_hpl  [(size_t)BS*NF];        // tanh-merge out (tf32, PERM)
__device__ float g_gh   [(size_t)BS*384];       // GRU hh gates (normal)
__device__ float g_odewT[NF*NF];
__device__ float g_gwih [384*512];              // tf32+PERM gru_w_ih
__device__ float g_gwhh2[384*128];              // tf32+PERM gru_w_hh
__device__ float g_wu   [1280*640];             // WU (tf32, K-PERM)
__device__ float g_cu   [1280];                 // u1 bias
__device__ float g_wq2  [128*640];              // outfn_w @ out_proj_w (fp32)
__device__ float g_w3   [128*640];              // attn_wq^T outfn out_proj (fp32)
__device__ float g_bq2  [128];
__device__ float g_w4   [128*1280];             // W3 folded with Wv (tf32, K-PERM)
__device__ float g_b4   [128];
__device__ float g_wk2  [384*128];              // attn_wk (tf32, K-PERM)
__device__ float g_wm2  [384*128];              // attn_wv @ merge_w_top (fp32)
__device__ float g_wcat [128*512];              // [Wm2; merge_w_bot]^T (tf32, K-PERM)

__device__ __forceinline__ uint32_t f2tf(float x) {
    uint32_t u; asm("cvt.rna.tf32.f32 %0, %1;" : "=r"(u) : "f"(x)); return u;
}
__device__ __forceinline__ float tfr(float x) { return __uint_as_float(f2tf(x)); }

__device__ __forceinline__ void cp16(uint32_t dst, const void* src) {
    asm volatile("cp.async.cg.shared.global [%0], [%1], 16;" :: "r"(dst), "l"(src));
}

// ---------------- TF32 mma.sync GEMM, TN form, K-interleaved operands -------
// C[M,N] = act(A[M,K] * B[N,K]^T + bias). PERMOUT: tf32+PERM'd col store.
template<bool PERMOUT, bool TANH>
__global__ __launch_bounds__(256, 2)
void tgemm(int K, const float* __restrict__ A, int lda,
           const float* __restrict__ B,
           float* __restrict__ C, int ldc,
           const float* __restrict__ bias)
{
    __shared__ float As[3][128][16];
    __shared__ float Bs[3][128][16];
    int tid = threadIdx.x;
    int warp = tid >> 5, lane = tid & 31;
    int row0 = blockIdx.y * 128, col0 = blockIdx.x * 128;
    int m0 = (warp >> 1) * 32, n0 = (warp & 1) * 64;
    int g = lane >> 2, t = lane & 3;

    float c[2][8][4];
#pragma unroll
    for (int mi = 0; mi < 2; mi++)
#pragma unroll
        for (int ni = 0; ni < 8; ni++)
#pragma unroll
            for (int i = 0; i < 4; i++) c[mi][ni][i] = 0.f;

    const float* Ap = A + (size_t)row0 * lda;
    const float* Bp = B + (size_t)col0 * K;

    uint32_t sA = (uint32_t)__cvta_generic_to_shared(&As[0][0][0]);
    uint32_t sB = (uint32_t)__cvta_generic_to_shared(&Bs[0][0][0]);
    const uint32_t stg = 128u*16u*4u;

#define LOADSTAGE(s, kt) {                                                    \
        _Pragma("unroll")                                                     \
        for (int i = 0; i < 2; i++) {                                         \
            int j = tid + i*256, r = j >> 2, q = j & 3;                       \
            cp16(sA + (uint32_t)(s)*stg + (uint32_t)(r*16 + q*4)*4u,          \
                 Ap + (size_t)r*lda + (kt)*16 + q*4);                         \
            cp16(sB + (uint32_t)(s)*stg + (uint32_t)(r*16 + q*4)*4u,          \
                 Bp + (size_t)r*K + (kt)*16 + q*4);                           \
        }                                                                     \
        asm volatile("cp.async.commit_group;" ::: "memory");                  \
    }

    int T = K >> 4;
    LOADSTAGE(0, 0);
    LOADSTAGE(1, 1);

    int s = 0, sw = 2;
    for (int kt = 0; kt < T; kt++) {
        if (kt + 1 < T) asm volatile("cp.async.wait_group 1;" ::: "memory");
        else            asm volatile("cp.async.wait_group 0;" ::: "memory");
        __syncthreads();
        if (kt + 2 < T) LOADSTAGE(sw, kt + 2);

        float4 av[2][2], bv[8];
#pragma unroll
        for (int mi = 0; mi < 2; mi++) {
            int rm = m0 + mi*16 + g;
            av[mi][0] = *(const float4*)&As[s][rm    ][t*4];
            av[mi][1] = *(const float4*)&As[s][rm + 8][t*4];
        }
#pragma unroll
        for (int ni = 0; ni < 8; ni++) {
            int cn = n0 + ni*8 + g;
            bv[ni] = *(const float4*)&Bs[s][cn][t*4];
        }
#pragma unroll
        for (int mi = 0; mi < 2; mi++)
#pragma unroll
            for (int ni = 0; ni < 8; ni++) {
                asm volatile(
                    "mma.sync.aligned.m16n8k8.row.col.f32.tf32.tf32.f32 "
                    "{%0,%1,%2,%3},{%4,%5,%6,%7},{%8,%9},{%0,%1,%2,%3};\n"
                    : "+f"(c[mi][ni][0]), "+f"(c[mi][ni][1]),
                      "+f"(c[mi][ni][2]), "+f"(c[mi][ni][3])
                    : "r"(__float_as_uint(av[mi][0].x)), "r"(__float_as_uint(av[mi][1].x)),
                      "r"(__float_as_uint(av[mi][0].y)), "r"(__float_as_uint(av[mi][1].y)),
                      "r"(__float_as_uint(bv[ni].x)),    "r"(__float_as_uint(bv[ni].y)));
                asm volatile(
                    "mma.sync.aligned.m16n8k8.row.col.f32.tf32.tf32.f32 "
                    "{%0,%1,%2,%3},{%4,%5,%6,%7},{%8,%9},{%0,%1,%2,%3};\n"
                    : "+f"(c[mi][ni][0]), "+f"(c[mi][ni][1]),
                      "+f"(c[mi][ni][2]), "+f"(c[mi][ni][3])
                    : "r"(__float_as_uint(av[mi][0].z)), "r"(__float_as_uint(av[mi][1].z)),
                      "r"(__float_as_uint(av[mi][0].w)), "r"(__float_as_uint(av[mi][1].w)),
                      "r"(__float_as_uint(bv[ni].z)),    "r"(__float_as_uint(bv[ni].w)));
            }
        __syncthreads();
        s  = (s  == 2) ? 0 : s  + 1;
        sw = (sw == 2) ? 0 : sw + 1;
    }

#pragma unroll
    for (int mi = 0; mi < 2; mi++) {
        size_t r1 = (size_t)(row0 + m0 + mi*16 + g);
        size_t r2 = r1 + 8;
#pragma unroll
        for (int ni = 0; ni < 8; ni++) {
            int cc = col0 + n0 + ni*8 + 2*t;
            float b0 = 0.f, b1 = 0.f;
            if (bias) { b0 = bias[cc]; b1 = bias[cc + 1]; }
            float v0 = c[mi][ni][0] + b0, v1 = c[mi][ni][1] + b1;
            float v2 = c[mi][ni][2] + b0, v3 = c[mi][ni][3] + b1;
            if (TANH) { v0 = tanhf(v0); v1 = tanhf(v1); v2 = tanhf(v2); v3 = tanhf(v3); }
            if (PERMOUT) {
                int p0 = PERM(cc), p1 = PERM(cc + 1);
                C[r1*ldc + p0] = tfr(v0); C[r1*ldc + p1] = tfr(v1);
                C[r2*ldc + p0] = tfr(v2); C[r2*ldc + p1] = tfr(v3);
            } else {
                *(float2*)&C[r1*ldc + cc] = make_float2(v0, v1);
                *(float2*)&C[r2*ldc + cc] = make_float2(v2, v3);
            }
        }
    }
#undef LOADSTAGE
}

// ---------------- generic small SIMT GEMM (precompute path) ------------------
template<bool TRANSA, bool TFPERM>
__global__ __launch_bounds__(256)
void sgemm_small(int M, int N, int K,
                 const float* __restrict__ A, int lda,
                 const float* __restrict__ B, int ldb,
                 float* __restrict__ C, int ldc)
{
    __shared__ float As[16][64];
    __shared__ float Bs[16][64];
    int tid = threadIdx.x;
    int m0 = blockIdx.y*64, n0 = blockIdx.x*64;
    int tx = tid & 15, ty = tid >> 4;
    float acc[4][4];
#pragma unroll
    for (int i = 0; i < 4; i++)
#pragma unroll
        for (int j = 0; j < 4; j++) acc[i][j] = 0.f;

    for (int k0 = 0; k0 < K; k0 += 16) {
        if (TRANSA) {
            for (int i = tid; i < 1024; i += 256) {
                int kk = i >> 6, mm = i & 63;
                As[kk][mm] = A[(size_t)(k0+kk)*lda + m0 + mm];
            }
        } else {
            for (int i = tid; i < 1024; i += 256) {
                int mm = i >> 4, kk = i & 15;
                As[kk][mm] = A[(size_t)(m0+mm)*lda + k0 + kk];
            }
        }
        for (int i = tid; i < 1024; i += 256) {
            int kk = i >> 6, nn = i & 63;
            Bs[kk][nn] = B[(size_t)(k0+kk)*ldb + n0 + nn];
        }
        __syncthreads();
#pragma unroll
        for (int kk = 0; kk < 16; kk++) {
            float4 a4 = *(const float4*)&As[kk][ty*4];
            float4 b4 = *(const float4*)&Bs[kk][tx*4];
            float a[4] = {a4.x, a4.y, a4.z, a4.w};
            float b[4] = {b4.x, b4.y, b4.z, b4.w};
#pragma unroll
            for (int i = 0; i < 4; i++)
#pragma unroll
                for (int j = 0; j < 4; j++)
                    acc[i][j] = fmaf(a[i], b[j], acc[i][j]);
        }
        __syncthreads();
    }
#pragma unroll
    for (int i = 0; i < 4; i++) {
        size_t m = (size_t)(m0 + ty*4 + i);
#pragma unroll
        for (int j = 0; j < 4; j++) {
            int n = n0 + tx*4 + j;
            if (TFPERM) C[m*ldc + PERM(n)] = tfr(acc[i][j]);
            else        C[m*ldc + n]       = acc[i][j];
        }
    }
}

// ---------------- build full_vals, nb, last_event_feat (tf32 + PERM) -------
__global__ void build_kernel(const int* __restrict__ nids,
                             const int* __restrict__ hist_nids,
                             const int* __restrict__ aids,
                             const int* __restrict__ eids,
                             const float* __restrict__ hist_ts,
                             const int* __restrict__ dirs,
                             const float* __restrict__ node_feat,
                             const float* __restrict__ edge_feat,
                             const float* __restrict__ anony,
                             const float* __restrict__ tw,
                             const float* __restrict__ tb)
{
    int bl = blockIdx.x;            // b*HL + l
    int b  = bl / HL, l = bl % HL;
    int j  = threadIdx.x;           // 0..127
    int jp = PERM(j);
    int hn  = hist_nids[bl];
    int dir = dirs[bl];
    int nid = nids[b];
    int src = dir ? nid : hn;
    int dst = dir ? hn  : nid;
    float sv = tfr(node_feat[(size_t)src*NF + j]);
    float dv = tfr(node_feat[(size_t)dst*NF + j]);
    float av = tfr(anony[(size_t)aids[bl]*NF + j]);
    float ev = tfr(edge_feat[(size_t)eids[bl]*EF + j]);
    float dt = hist_ts[b*HL + HL-1] - hist_ts[bl];
    float tv = tfr(cosf(dt*tw[j] + tb[j]));

    float* fv = g_full + (size_t)bl*DM;
    if (l == HL-1) {
        float* lef = g_lef + (size_t)b*DIN;
        lef[jp] = sv; lef[NF+jp] = dv; lef[2*NF+jp] = av; lef[3*NF+jp] = ev;
        fv[jp] = 0.f; fv[NF+jp] = 0.f; fv[2*NF+jp] = 0.f; fv[3*NF+jp] = 0.f;
        fv[4*NF+jp] = tv;
    } else {
        fv[jp] = sv; fv[NF+jp] = dv; fv[2*NF+jp] = av; fv[3*NF+jp] = ev;
        fv[4*NF+jp] = tv;
    }
    float* nb = g_nb + (size_t)bl*384;
    nb[jp]        = tfr(node_feat[(size_t)hn*NF + j]);
    nb[NF + jp]   = ev;
    nb[2*NF + jp] = tv;
}

__global__ void transpose_odew(const float* __restrict__ w)
{
    int idx = blockIdx.x*128 + threadIdx.x;
    int j = idx >> 7, k = idx & 127;
    g_odewT[k*NF + j] = w[idx];
}

// tf32-round + K-permute columns of a row-major [rows, K] matrix
__global__ void cvt_tf32p(const float* __restrict__ s, float* __restrict__ d,
                          int K, int n)
{
    int i = blockIdx.x*256 + threadIdx.x;
    if (i < n) {
        int row = i / K, col = i % K;
        d[(size_t)row*K + PERM(col)] = tfr(s[i]);
    }
}

// Wcat[o, PERM(k)] = k<384 ? Wm2[k,o] : merge_w[(128 + k-384)*128 + o]
__global__ void wcat_build(const float* __restrict__ mw)
{
    int i = blockIdx.x*256 + threadIdx.x;   // 128*512
    if (i >= 128*512) return;
    int o = i >> 9, k = i & 511;
    float v = (k < 384) ? g_wm2[(size_t)k*128 + o]
                        : mw[(size_t)(128 + k - 384)*128 + o];
    g_wcat[(size_t)o*512 + PERM(k)] = tfr(v);
}

// ---------------- bias precomputes (block-per-output reductions) ------------
__device__ __forceinline__ float block_reduce(float s)
{
    __shared__ float red[4];
    for (int o = 16; o; o >>= 1) s += __shfl_xor_sync(0xffffffffu, s, o);
    if ((threadIdx.x & 31) == 0) red[threadIdx.x >> 5] = s;
    __syncthreads();
    return red[0] + red[1] + red[2] + red[3];
}

__global__ void cu_build(const float* __restrict__ ipw, const float* __restrict__ ipb)
{
    int n = blockIdx.x;                 // grid 1280
    int h = n / 640, d = n - h*640;
    float s = 0.f;
    for (int i = threadIdx.x; i < 320; i += 128)
        s += ipb[320*h + i] * ipw[(size_t)(640 + 320*h + i)*640 + d];
    float tot = block_reduce(s);
    if (threadIdx.x == 0) g_cu[n] = tot;
}

__global__ void bq2_build(const float* __restrict__ opb,
                          const float* __restrict__ outfn_w,
                          const float* __restrict__ outfn_b)
{
    int i = blockIdx.x;                 // grid 128
    float s = 0.f;
    for (int k = threadIdx.x; k < 640; k += 128)
        s += opb[k] * outfn_w[(size_t)i*640 + k];
    float tot = block_reduce(s);
    if (threadIdx.x == 0) g_bq2[i] = outfn_b[i] + tot;
}

__global__ void b4_build(const float* __restrict__ awq, const float* __restrict__ ipb)
{
    int o = blockIdx.x;                 // grid 128
    int t = threadIdx.x;
    float s = g_bq2[t] * awq[(size_t)t*128 + o];
    for (int m = t; m < 640; m += 128)
        s += g_w3[(size_t)o*640 + m] * ipb[1280 + m];
    float tot = block_reduce(s);
    if (threadIdx.x == 0) g_b4[o] = tot;
}

// ---------------- attention 1: f cached in smem, both heads share reads -----
__global__ __launch_bounds__(256)
void attn1_kernel(const int* __restrict__ hist_nids)
{
    extern __shared__ float asm1[];     // sf[12800] + su[1280] + sS[40] + sA[40]
    float* sf = asm1;
    float* su = asm1 + HL*DM;
    float* sS = su + 1280;
    float* sA = sS + 40;
    int b = blockIdx.x, tid = threadIdx.x;

    {   // load f tile (PERM space) once
        const float4* src = (const float4*)(g_full + (size_t)b*HL*DM);
        float4* dst = (float4*)sf;
        for (int i = tid; i < HL*DM/4; i += 256) dst[i] = src[i];
        for (int x = tid; x < 1280; x += 256)
            su[x] = g_u1[(size_t)b*1280 + PERM(x)];
    }
    __syncthreads();

    int warp = tid >> 5, lane = tid & 31;
    for (int m = warp; m < HL; m += 8) {
        const float* frow = sf + m*DM;
        float s0 = 0.f, s1 = 0.f;
#pragma unroll
        for (int i = 0; i < 20; i++) {
            int d = lane + i*32;
            float f = frow[d];
            s0 += su[d]*f; s1 += su[DM + d]*f;
        }
#pragma unroll
        for (int o = 16; o; o >>= 1) {
            s0 += __shfl_xor_sync(0xffffffffu, s0, o);
            s1 += __shfl_xor_sync(0xffffffffu, s1, o);
        }
        if (!lane) {
            sS[m]      = s0 * 0.05590169943749474f;   // 1/sqrt(320)
            sS[HL + m] = s1 * 0.05590169943749474f;
        }
    }
    __syncthreads();
    if (tid < NHEAD) {
        int h = tid;
        float sc[HL], mx = -1e30f;
        for (int m = 0; m < HL; m++) {
            float v = sS[h*HL + m];
            if (hist_nids[b*HL + m] == 0 && m != HL-1) v = -1e9f;
            sc[m] = v; mx = fmaxf(mx, v);
        }
        float sum = 0.f;
        for (int m = 0; m < HL; m++) { float e = expf(sc[m]-mx); sc[m] = e; sum += e; }
        float inv = 1.f/sum;
        for (int m = 0; m < HL; m++) sA[h*HL + m] = sc[m]*inv;
    }
    __syncthreads();
    for (int e = tid; e < DM; e += 256) {
        float a0 = 0.f, a1 = 0.f;
#pragma unroll
        for (int m = 0; m < HL; m++) {
            float f = sf[m*DM + e];
            a0 += sA[m]*f; a1 += sA[HL + m]*f;
        }
        g_s[(size_t)b*1280 + e]      = tfr(a0);
        g_s[(size_t)b*1280 + DM + e] = tfr(a1);
    }
}

// ---------------- attention 2: scores + weighted sums -> cat2 ---------------
__global__ __launch_bounds__(128)
void attn2_kernel(const int* __restrict__ nids,
                  const int* __restrict__ hist_nids,
                  const float* __restrict__ node_feat)
{
    __shared__ float snb[HL*384];       // 30KB: nb tile cached
    __shared__ float su2[384], sS[HL], sA[HL];
    int b = blockIdx.x, tid = threadIdx.x;
    {
        const float4* src = (const float4*)(g_nb + (size_t)b*HL*384);
        float4* dst = (float4*)snb;
        for (int i = tid; i < HL*384/4; i += 128) dst[i] = src[i];
#pragma unroll
        for (int q = 0; q < 3; q++)
            su2[tid + q*128] = g_u2[(size_t)b*384 + tid + q*128];
    }
    float nf = tfr(node_feat[(size_t)nids[b]*NF + tid]);
    __syncthreads();

    int warp = tid >> 5, lane = tid & 31;
    for (int l = warp; l < HL; l += 4) {
        const float* nr = snb + l*384;
        float s = 0.f;
#pragma unroll
        for (int i = 0; i < 12; i++) { int d = lane + i*32; s += su2[d]*nr[d]; }
#pragma unroll
        for (int o = 16; o; o >>= 1) s += __shfl_xor_sync(0xffffffffu, s, o);
        if (!lane) sS[l] = s * 0.08838834764831845f;  // 1/sqrt(128)
    }
    __syncthreads();
    if (tid == 0) {
        float sc[HL], mx = -1e30f;
        for (int l = 0; l < HL; l++) {
            float v = sS[l];
            if (hist_nids[b*HL + l] == 0 && l != HL-1) v = -1e9f;
            sc[l] = v; mx = fmaxf(mx, v);
        }
        float sum = 0.f;
        for (int l = 0; l < HL; l++) { float e = expf(sc[l]-mx); sc[l] = e; sum += e; }
        float inv = 1.f/sum;
        for (int l = 0; l < HL; l++) sA[l] = sc[l]*inv;
    }
    __syncthreads();
    float* cat = g_cat2 + (size_t)b*512;
#pragma unroll
    for (int q = 0; q < 3; q++) {
        int x = tid + q*128;               // PERM-space index into snb
        float acc = 0.f;
#pragma unroll
        for (int l = 0; l < HL; l++) acc += sA[l] * snb[l*384 + x];
        cat[x] = tfr(acc);                 // already PERM space: store directly
    }
    cat[384 + PERM(tid)] = nf;             // nf: normal tid -> PERM position
}

// ---------------- ODE (RK4) + fused GRU elementwise, 8 samples/block --------
__global__ __launch_bounds__(128)
void ode_kernel(const float* __restrict__ hist_ts,
                const float* __restrict__ tnw,
                const float* __restrict__ tnb,
                const float* __restrict__ odeb,
                float* __restrict__ out)
{
    extern __shared__ float sm[];           // wsm[16384] + ysm[128*8]
    float* wsm = sm;
    float* ysm = sm + NF*NF;
    int j = threadIdx.x;
    int b0 = blockIdx.x * 8;

    for (int i = j; i < NF*NF; i += 128) wsm[i] = g_odewT[i];
    float tw = tnw[j], tb = tnb[j], ob = odeb[j];
    int jp = PERM(j);
    float t0v[8], rat[8], z[8];
#pragma unroll
    for (int s = 0; s < 8; s++) {
        int b = b0 + s;
        float a = hist_ts[b*HL + HL-2];
        float bb = hist_ts[b*HL + HL-1];
        t0v[s] = a; rat[s] = bb - a;
        // fused GRU elementwise
        const float* gi = g_gi + (size_t)b*384;
        const float* gh = g_gh + (size_t)b*384;
        float hpl = g_hpl[(size_t)b*NF + jp];
        float r  = 1.f/(1.f + expf(-(gi[j]        + gh[j])));
        float zg = 1.f/(1.f + expf(-(gi[NF + j]   + gh[NF + j])));
        float n  = tanhf(gi[2*NF + j] + r*gh[2*NF + j]);
        float hpr = (1.f - zg)*n + zg*hpl;
        z[s] = hpr;
        out[(size_t)BS*NF + (size_t)b*NF + j] = hpr;   // h_right
    }
    if (j < 8) out[(size_t)2*BS*NF + b0 + j] = hist_ts[(b0+j)*HL + HL-1];
    __syncthreads();
    const float ds = 1.f/ODE_STEPS;

    auto fstage = [&](float sfrac, const float* zi, float* f) {
        __syncthreads();
#pragma unroll
        for (int s = 0; s < 8; s++) {
            float te = __cosf((sfrac*rat[s] + t0v[s])*tw + tb);
            ysm[j*8 + s] = zi[s] + te;
        }
        __syncthreads();
        float acc[8];
#pragma unroll
        for (int s = 0; s < 8; s++) acc[s] = ob;
#pragma unroll 4
        for (int k = 0; k < NF; k++) {
            float w = wsm[k*NF + j];
            float4 y0 = *(const float4*)&ysm[k*8];
            float4 y1 = *(const float4*)&ysm[k*8 + 4];
            acc[0] = fmaf(y0.x, w, acc[0]);
            acc[1] = fmaf(y0.y, w, acc[1]);
            acc[2] = fmaf(y0.z, w, acc[2]);
            acc[3] = fmaf(y0.w, w, acc[3]);
            acc[4] = fmaf(y1.x, w, acc[4]);
            acc[5] = fmaf(y1.y, w, acc[5]);
            acc[6] = fmaf(y1.z, w, acc[6]);
            acc[7] = fmaf(y1.w, w, acc[7]);
        }
#pragma unroll
        for (int s = 0; s < 8; s++) {
            float th;
            asm("tanh.approx.f32 %0, %1;" : "=f"(th) : "f"(acc[s]));
            f[s] = th * rat[s];
        }
    };

    for (int i = 0; i < ODE_STEPS; i++) {
        float s0 = i * ds;
        float k1[8], k2[8], k3[8], k4[8], zi[8];
        fstage(s0, z, k1);
#pragma unroll
        for (int s = 0; s < 8; s++) zi[s] = z[s] + 0.5f*ds*k1[s];
        fstage(s0 + 0.5f*ds, zi, k2);
#pragma unroll
        for (int s = 0; s < 8; s++) zi[s] = z[s] + 0.5f*ds*k2[s];
        fstage(s0 + 0.5f*ds, zi, k3);
#pragma unroll
        for (int s = 0; s < 8; s++) zi[s] = z[s] + ds*k3[s];
        fstage(s0 + ds, zi, k4);
#pragma unroll
        for (int s = 0; s < 8; s++)
            z[s] += ds/6.f * (k1[s] + 2.f*k2[s] + 2.f*k3[s] + k4[s]);
    }
#pragma unroll
    for (int s = 0; s < 8; s++)
        out[(size_t)(b0+s)*NF + j] = z[s];   // h_left
}

// ---------------- host ------------------------------------------------------
extern "C" void kernel_launch(void* const* d_in, const int* in_sizes, int n_in,
                              void* d_out, int out_size)
{
    const int*   nids       = (const int*)  d_in[0];
    const int*   hist_nids  = (const int*)  d_in[2];
    const int*   aids       = (const int*)  d_in[3];
    const int*   eids       = (const int*)  d_in[4];
    const float* hist_ts    = (const float*)d_in[5];
    const int*   dirs       = (const int*)  d_in[6];
    const float* node_feat  = (const float*)d_in[7];
    const float* edge_feat  = (const float*)d_in[8];
    const float* anony_emb  = (const float*)d_in[9];
    const float* time_w     = (const float*)d_in[10];
    const float* time_b     = (const float*)d_in[11];
    const float* in_proj_w  = (const float*)d_in[12];
    const float* in_proj_b  = (const float*)d_in[13];
    const float* out_proj_w = (const float*)d_in[14];
    const float* out_proj_b = (const float*)d_in[15];
    const float* outfn_w    = (const float*)d_in[16];
    const float* outfn_b    = (const float*)d_in[17];
    const float* attn_wq    = (const float*)d_in[18];
    const float* attn_wk    = (const float*)d_in[19];
    const float* attn_wv    = (const float*)d_in[20];
    const float* merge_w    = (const float*)d_in[21];
    const float* merge_b    = (const float*)d_in[22];
    const float* gru_w_ih   = (const float*)d_in[23];
    const float* gru_w_hh   = (const float*)d_in[24];
    const float* gru_b_ih   = (const float*)d_in[25];
    const float* gru_b_hh   = (const float*)d_in[26];
    const float* ode_w      = (const float*)d_in[27];
    const float* ode_b      = (const float*)d_in[28];
    const float* tnode_w    = (const float*)d_in[29];
    const float* tnode_b    = (const float*)d_in[30];

    float* out = (float*)d_out;

    float *p_full, *p_lef, *p_u1, *p_s, *p_qh, *p_u2, *p_gi, *p_cat2, *p_hpl,
          *p_gh, *p_gwih, *p_gwhh2, *p_wu, *p_cu, *p_wq2, *p_w3, *p_w4, *p_b4,
          *p_wk2, *p_wm2, *p_wcat;
    cudaGetSymbolAddress((void**)&p_full,  g_full);
    cudaGetSymbolAddress((void**)&p_lef,   g_lef);
    cudaGetSymbolAddress((void**)&p_u1,    g_u1);
    cudaGetSymbolAddress((void**)&p_s,     g_s);
    cudaGetSymbolAddress((void**)&p_qh,    g_qh);
    cudaGetSymbolAddress((void**)&p_u2,    g_u2);
    cudaGetSymbolAddress((void**)&p_gi,    g_gi);
    cudaGetSymbolAddress((void**)&p_cat2,  g_cat2);
    cudaGetSymbolAddress((void**)&p_hpl,   g_hpl);
    cudaGetSymbolAddress((void**)&p_gh,    g_gh);
    cudaGetSymbolAddress((void**)&p_gwih,  g_gwih);
    cudaGetSymbolAddress((void**)&p_gwhh2, g_gwhh2);
    cudaGetSymbolAddress((void**)&p_wu,    g_wu);
    cudaGetSymbolAddress((void**)&p_cu,    g_cu);
    cudaGetSymbolAddress((void**)&p_wq2,   g_wq2);
    cudaGetSymbolAddress((void**)&p_w3,    g_w3);
    cudaGetSymbolAddress((void**)&p_w4,    g_w4);
    cudaGetSymbolAddress((void**)&p_b4,    g_b4);
    cudaGetSymbolAddress((void**)&p_wk2,   g_wk2);
    cudaGetSymbolAddress((void**)&p_wm2,   g_wm2);
    cudaGetSymbolAddress((void**)&p_wcat,  g_wcat);

    cudaFuncSetAttribute(ode_kernel, cudaFuncAttributeMaxDynamicSharedMemorySize,
                         (NF*NF + NF*8) * 4);
    cudaFuncSetAttribute(attn1_kernel, cudaFuncAttributeMaxDynamicSharedMemorySize,
                         (HL*DM + 1280 + 80) * 4);

    // --- gather (big, parallel) ---
    build_kernel<<<BS*HL, 128>>>(nids, hist_nids, aids, eids, hist_ts, dirs,
                                 node_feat, edge_feat, anony_emb, time_w, time_b);

    // --- precompute (wide-parallel) ---
    transpose_odew<<<128, 128>>>(ode_w);
    cvt_tf32p<<<(384*512 + 255)/256, 256>>>(gru_w_ih, p_gwih, 512, 384*512);
    cvt_tf32p<<<(384*128 + 255)/256, 256>>>(attn_wk, p_wk2, 128, 384*128);
    cvt_tf32p<<<(384*128 + 255)/256, 256>>>(gru_w_hh, p_gwhh2, 128, 384*128);

    for (int h = 0; h < 2; h++)
        sgemm_small<true, true><<<dim3(10, 10), 256>>>(
            640, 640, 320,
            in_proj_w + (size_t)(640 + 320*h)*640, 640,
            in_proj_w + (size_t)(320*h)*640, 640,
            p_wu + (size_t)(640*h)*640, 640);
    cu_build<<<1280, 128>>>(in_proj_w, in_proj_b);

    sgemm_small<false, false><<<dim3(10, 2), 256>>>(
        128, 640, 640, outfn_w, 640, out_proj_w, 640, p_wq2, 640);
    sgemm_small<true, false><<<dim3(10, 2), 256>>>(
        128, 640, 128, attn_wq, 128, p_wq2, 640, p_w3, 640);
    for (int h = 0; h < 2; h++)
        sgemm_small<false, true><<<dim3(10, 2), 256>>>(
            128, 640, 320,
            p_w3 + 320*h, 640,
            in_proj_w + (size_t)(1280 + 320*h)*640, 640,
            p_w4 + 640*h, 1280);
    bq2_build<<<128, 128>>>(out_proj_b, outfn_w, outfn_b);
    b4_build<<<128, 128>>>(attn_wq, in_proj_b);

    sgemm_small<false, false><<<dim3(2, 6), 256>>>(
        384, 128, 128, attn_wv, 128, merge_w, 128, p_wm2, 128);
    wcat_build<<<(128*512 + 255)/256, 256>>>(merge_w);

    // --- gi = lef @ gru_w_ih^T ---
    tgemm<false,false><<<dim3(3, 32), 256>>>(DIN, p_lef, DIN, p_gwih, p_gi,
                                             384, gru_b_ih);

    // --- u1 = full_last @ WU^T + cu ---
    tgemm<false,false><<<dim3(10, 32), 256>>>(DM, p_full + (size_t)(HL-1)*DM,
                                              HL*DM, p_wu, p_u1, 1280, p_cu);

    // --- attention 1 (f cached in smem) ---
    attn1_kernel<<<BS, 256, (HL*DM + 1280 + 80)*4>>>(hist_nids);

    // --- qh = s @ W4^T + b4 (PERM out) ---
    tgemm<true,false><<<dim3(1, 32), 256>>>(1280, p_s, 1280, p_w4, p_qh, NF, p_b4);

    // --- u2 = qh @ attn_wk^T (PERM out) ---
    tgemm<true,false><<<dim3(3, 32), 256>>>(NF, p_qh, NF, p_wk2, p_u2, 384,
                                            (const float*)nullptr);

    // --- attention 2 -> cat2 ---
    attn2_kernel<<<BS, 128>>>(nids, hist_nids, node_feat);

    // --- hpl = tanh(cat2 @ Wcat^T + merge_b) (PERM out) ---
    tgemm<true,true><<<dim3(1, 32), 256>>>(512, p_cat2, 512, p_wcat, p_hpl,
                                           NF, merge_b);

    // --- gh = hpl @ gru_w_hh^T + b_hh ---
    tgemm<false,false><<<dim3(3, 32), 256>>>(NF, p_hpl, NF, p_gwhh2, p_gh,
                                             384, gru_b_hh);

    // --- ODE RK4 + fused GRU (writes h_left, h_right, ts) ---
    ode_kernel<<<BS/8, 128, (NF*NF + NF*8)*4>>>(hist_ts, tnode_w, tnode_b,
                                                ode_b, out);
}